// round 5
// baseline (speedup 1.0000x reference)
#include <cuda_runtime.h>
#include <cstdint>

#define NPIX   131072          // B*H*W
#define NBATCH 65536           // H*W
#define HH_    64
#define WW_    1024
#define C1_    64
#define C2_    128
#define CIN_   192
#define CMID_  128
#define INV_M  (1.0f/131072.0f)
#define BN_EPS_ 1e-5f

// -------- scratch (device globals; no allocs allowed) --------
__device__ float g_x[(size_t)NPIX * CIN_];      // concat [feat1 | interp]
__device__ float g_y1[(size_t)NPIX * CMID_];    // layer-0 pre-BN output
__device__ int   g_sel[NPIX * 3];
__device__ float g_coef[NPIX * 3];
__device__ float g_sum0[128], g_ss0[128], g_sum1[128], g_ss1[128];
__device__ float g_a0[128], g_d0[128], g_a1[128], g_d1[128];

// -------- zero per-channel stat accumulators --------
__global__ void zero_stats_kernel() {
    int c = threadIdx.x;
    g_sum0[c] = 0.f; g_ss0[c] = 0.f;
    g_sum1[c] = 0.f; g_ss1[c] = 0.f;
}

// -------- grid KNN: first-3-valid in 5x5 window, inverse-distance coefs --------
__global__ void knn_kernel(const float* __restrict__ xyz1,
                           const float* __restrict__ xyz2) {
    int idx = blockIdx.x * blockDim.x + threadIdx.x;   // 0..131071
    int b = idx >> 16;
    int n = idx & (NBATCH - 1);
    int h = n >> 10;
    int w = n & (WW_ - 1);

    const float* q = xyz1 + (size_t)idx * 3;
    float qx = q[0], qy = q[1], qz = q[2];

    int   sel[3] = {0, 0, 0};
    float mk[3]  = {0.f, 0.f, 0.f};
    int cnt = 0;

    #pragma unroll
    for (int dh = -2; dh <= 2; dh++) {
        int hh = h + dh;
        if (hh < 0 || hh >= HH_) continue;
        #pragma unroll
        for (int dw = -2; dw <= 2; dw++) {
            int ww = w + dw;
            if (ww < 0 || ww >= WW_) continue;
            int nn = (hh << 10) + ww;
            const float* p = xyz2 + ((size_t)b * NBATCH + nn) * 3;
            float dx = p[0] - qx, dy = p[1] - qy, dz = p[2] - qz;
            float d2 = dx * dx + dy * dy + dz * dz;
            if (d2 < 10000.0f && cnt < 3) {
                sel[cnt] = nn; mk[cnt] = 1.f; cnt++;
            }
        }
    }

    // inverse-distance weights; invalid slots use masked (zero) neighbor, per reference
    float inv[3]; float dsum = 0.f;
    #pragma unroll
    for (int s = 0; s < 3; s++) {
        const float* p = xyz2 + ((size_t)b * NBATCH + sel[s]) * 3;
        float gx = p[0] * mk[s], gy = p[1] * mk[s], gz = p[2] * mk[s];
        float dx = gx - qx, dy = gy - qy, dz = gz - qz;
        float d2 = dx * dx + dy * dy + dz * dz;
        if (d2 < 1e-10f) d2 = 1e-10f;
        inv[s] = 1.0f / d2;
        dsum += inv[s];
    }
    float rnorm = 1.0f / dsum;
    #pragma unroll
    for (int s = 0; s < 3; s++) {
        g_sel[idx * 3 + s]  = b * NBATCH + sel[s];
        g_coef[idx * 3 + s] = inv[s] * rnorm * mk[s];
    }
}

// -------- build x = [feat1 | interp]  (one block per pixel, 192 threads) --------
__global__ void buildx_kernel(const float* __restrict__ feat1,
                              const float* __restrict__ feat2) {
    int pix = blockIdx.x;
    int c = threadIdx.x;       // 0..191
    float v;
    if (c < C1_) {
        v = feat1[(size_t)pix * C1_ + c];
    } else {
        int c2 = c - C1_;
        int   s0 = g_sel[pix * 3 + 0], s1 = g_sel[pix * 3 + 1], s2 = g_sel[pix * 3 + 2];
        float c0 = g_coef[pix * 3 + 0], cc1 = g_coef[pix * 3 + 1], cc2 = g_coef[pix * 3 + 2];
        v = c0  * feat2[(size_t)s0 * C2_ + c2]
          + cc1 * feat2[(size_t)s1 * C2_ + c2]
          + cc2 * feat2[(size_t)s2 * C2_ + c2];
    }
    g_x[(size_t)pix * CIN_ + c] = v;
}

// -------- fp32 GEMM  Y[M,128] = act(A)[M,K] @ B[K,128] + bias, with channel stats --------
// ACT: apply relu(aa[k]*A + ad[k]) on A elements at load (layer-0 BN+ReLU fused)
template<int K, bool ACT>
__global__ __launch_bounds__(256, 2)
void gemm_bias_stats(const float* __restrict__ A, const float* __restrict__ B,
                     const float* __restrict__ bias,
                     const float* __restrict__ aa, const float* __restrict__ ad,
                     float* __restrict__ Y,
                     float* __restrict__ gsum, float* __restrict__ gss) {
    __shared__ float As[16][132];
    __shared__ float Bs[16][128];
    __shared__ float shS[128], shQ[128];

    const int tid = threadIdx.x;
    const int m0  = blockIdx.x * 128;
    const int tx  = tid & 15;        // col group (8 cols)
    const int ty  = tid >> 4;        // row group (8 rows)

    float acc[8][8];
    #pragma unroll
    for (int i = 0; i < 8; i++)
        #pragma unroll
        for (int j = 0; j < 8; j++) acc[i][j] = 0.f;

    const int arow = tid >> 2;       // 0..63
    const int akq  = tid & 3;        // 0..3 (float4 within 16-k slab)
    const int brow = tid >> 5;       // 0..7
    const int bc4  = tid & 31;       // 0..31

    for (int kt = 0; kt < K; kt += 16) {
        // A tile: 128 rows x 16 k, transposed store
        #pragma unroll
        for (int i = 0; i < 2; i++) {
            int r = arow + i * 64;
            float4 v = *reinterpret_cast<const float4*>(
                A + (size_t)(m0 + r) * K + kt + akq * 4);
            if (ACT) {
                int kg = kt + akq * 4;
                v.x = fmaxf(aa[kg + 0] * v.x + ad[kg + 0], 0.f);
                v.y = fmaxf(aa[kg + 1] * v.y + ad[kg + 1], 0.f);
                v.z = fmaxf(aa[kg + 2] * v.z + ad[kg + 2], 0.f);
                v.w = fmaxf(aa[kg + 3] * v.w + ad[kg + 3], 0.f);
            }
            As[akq * 4 + 0][r] = v.x;
            As[akq * 4 + 1][r] = v.y;
            As[akq * 4 + 2][r] = v.z;
            As[akq * 4 + 3][r] = v.w;
        }
        // B tile: 16 x 128, direct
        #pragma unroll
        for (int i = 0; i < 2; i++) {
            int r = brow + i * 8;
            *reinterpret_cast<float4*>(&Bs[r][bc4 * 4]) =
                *reinterpret_cast<const float4*>(B + (size_t)(kt + r) * 128 + bc4 * 4);
        }
        __syncthreads();

        #pragma unroll
        for (int kk = 0; kk < 16; kk++) {
            float af[8], bf[8];
            #pragma unroll
            for (int i = 0; i < 8; i++) af[i] = As[kk][ty * 8 + i];
            #pragma unroll
            for (int j = 0; j < 8; j++) bf[j] = Bs[kk][tx * 8 + j];
            #pragma unroll
            for (int i = 0; i < 8; i++)
                #pragma unroll
                for (int j = 0; j < 8; j++)
                    acc[i][j] += af[i] * bf[j];
        }
        __syncthreads();
    }

    // epilogue: bias, store (vectorized), per-channel sum/sumsq
    if (tid < 128) { shS[tid] = 0.f; shQ[tid] = 0.f; }
    __syncthreads();

    float bj[8];
    #pragma unroll
    for (int j = 0; j < 8; j++) bj[j] = bias[tx * 8 + j];

    float sj[8], qj[8];
    #pragma unroll
    for (int j = 0; j < 8; j++) { sj[j] = 0.f; qj[j] = 0.f; }

    #pragma unroll
    for (int i = 0; i < 8; i++) {
        float vv[8];
        #pragma unroll
        for (int j = 0; j < 8; j++) {
            vv[j] = acc[i][j] + bj[j];
            sj[j] += vv[j];
            qj[j] += vv[j] * vv[j];
        }
        float4* yp = reinterpret_cast<float4*>(
            Y + (size_t)(m0 + ty * 8 + i) * 128 + tx * 8);
        yp[0] = make_float4(vv[0], vv[1], vv[2], vv[3]);
        yp[1] = make_float4(vv[4], vv[5], vv[6], vv[7]);
    }
    #pragma unroll
    for (int j = 0; j < 8; j++) {
        atomicAdd(&shS[tx * 8 + j], sj[j]);
        atomicAdd(&shQ[tx * 8 + j], qj[j]);
    }
    __syncthreads();
    if (tid < 128) {
        atomicAdd(&gsum[tid], shS[tid]);
        atomicAdd(&gss[tid], shQ[tid]);
    }
}

// -------- finalize BN affine: a = g*rsqrt(var+eps), d = be - mu*a --------
__global__ void finalize_stats(const float* __restrict__ gsum, const float* __restrict__ gss,
                               const float* __restrict__ g, const float* __restrict__ be,
                               float* __restrict__ a, float* __restrict__ d) {
    int c = threadIdx.x;
    float mu  = gsum[c] * INV_M;
    float var = gss[c] * INV_M - mu * mu;
    float s = g[c] * rsqrtf(var + BN_EPS_);
    a[c] = s;
    d[c] = be[c] - mu * s;
}

// -------- final BN+ReLU, in place on d_out (float4) --------
__global__ void bn_out_kernel(float* __restrict__ out,
                              const float* __restrict__ a, const float* __restrict__ d) {
    int i = blockIdx.x * blockDim.x + threadIdx.x;   // float4 index
    int c = (i * 4) & 127;
    float4 v = reinterpret_cast<float4*>(out)[i];
    v.x = fmaxf(a[c + 0] * v.x + d[c + 0], 0.f);
    v.y = fmaxf(a[c + 1] * v.y + d[c + 1], 0.f);
    v.z = fmaxf(a[c + 2] * v.z + d[c + 2], 0.f);
    v.w = fmaxf(a[c + 3] * v.w + d[c + 3], 0.f);
    reinterpret_cast<float4*>(out)[i] = v;
}

extern "C" void kernel_launch(void* const* d_in, const int* in_sizes, int n_in,
                              void* d_out, int out_size) {
    const float* xyz1  = (const float*)d_in[0];
    const float* xyz2  = (const float*)d_in[1];
    const float* feat1 = (const float*)d_in[2];
    const float* feat2 = (const float*)d_in[3];
    const float* w0    = (const float*)d_in[4];
    const float* b0    = (const float*)d_in[5];
    const float* gg0   = (const float*)d_in[6];
    const float* be0   = (const float*)d_in[7];
    const float* w1    = (const float*)d_in[8];
    const float* b1    = (const float*)d_in[9];
    const float* gg1   = (const float*)d_in[10];
    const float* be1   = (const float*)d_in[11];
    float* out = (float*)d_out;

    float *p_x, *p_y1, *p_sum0, *p_ss0, *p_sum1, *p_ss1, *p_a0, *p_d0, *p_a1, *p_d1;
    cudaGetSymbolAddress((void**)&p_x,    g_x);
    cudaGetSymbolAddress((void**)&p_y1,   g_y1);
    cudaGetSymbolAddress((void**)&p_sum0, g_sum0);
    cudaGetSymbolAddress((void**)&p_ss0,  g_ss0);
    cudaGetSymbolAddress((void**)&p_sum1, g_sum1);
    cudaGetSymbolAddress((void**)&p_ss1,  g_ss1);
    cudaGetSymbolAddress((void**)&p_a0,   g_a0);
    cudaGetSymbolAddress((void**)&p_d0,   g_d0);
    cudaGetSymbolAddress((void**)&p_a1,   g_a1);
    cudaGetSymbolAddress((void**)&p_d1,   g_d1);

    zero_stats_kernel<<<1, 128>>>();
    knn_kernel<<<NPIX / 256, 256>>>(xyz1, xyz2);
    buildx_kernel<<<NPIX, 192>>>(feat1, feat2);

    gemm_bias_stats<192, false><<<NPIX / 128, 256>>>(
        p_x, w0, b0, nullptr, nullptr, p_y1, p_sum0, p_ss0);
    finalize_stats<<<1, 128>>>(p_sum0, p_ss0, gg0, be0, p_a0, p_d0);

    gemm_bias_stats<128, true><<<NPIX / 128, 256>>>(
        p_y1, w1, b1, p_a0, p_d0, out, p_sum1, p_ss1);
    finalize_stats<<<1, 128>>>(p_sum1, p_ss1, gg1, be1, p_a1, p_d1);

    bn_out_kernel<<<(NPIX * 128 / 4) / 256, 256>>>(out, p_a1, p_d1);
}

// round 9
// speedup vs baseline: 1.0159x; 1.0159x over previous
#include <cuda_runtime.h>
#include <cuda_bf16.h>
#include <cstdint>

#define NPIX   131072          // B*H*W
#define NBATCH 65536           // H*W
#define HH_    64
#define WW_    1024
#define C1_    64
#define C2_    128
#define INV_M  (1.0f/131072.0f)
#define BN_EPS_ 1e-5f

// stride (elements) of padded smem tiles: 64 data + 8 pad  -> 144B rows
#define LDS_  72

__device__ __forceinline__ uint32_t smem_u32(const void* p) {
    uint32_t a;
    asm("{ .reg .u64 t; cvta.to.shared.u64 t, %1; cvt.u32.u64 %0, t; }" : "=r"(a) : "l"(p));
    return a;
}

__device__ __forceinline__ void ldm_x4(uint32_t* r, uint32_t addr) {
    asm volatile("ldmatrix.sync.aligned.m8n8.x4.shared.b16 {%0,%1,%2,%3}, [%4];"
        : "=r"(r[0]), "=r"(r[1]), "=r"(r[2]), "=r"(r[3]) : "r"(addr));
}
__device__ __forceinline__ void ldm_x2(uint32_t* r, uint32_t addr) {
    asm volatile("ldmatrix.sync.aligned.m8n8.x2.shared.b16 {%0,%1}, [%2];"
        : "=r"(r[0]), "=r"(r[1]) : "r"(addr));
}
__device__ __forceinline__ void mma_bf16(float* c, const uint32_t* a, const uint32_t* b) {
    asm volatile("mma.sync.aligned.m16n8k16.row.col.f32.bf16.bf16.f32 "
        "{%0,%1,%2,%3}, {%4,%5,%6,%7}, {%8,%9}, {%0,%1,%2,%3};"
        : "+f"(c[0]), "+f"(c[1]), "+f"(c[2]), "+f"(c[3])
        : "r"(a[0]), "r"(a[1]), "r"(a[2]), "r"(a[3]), "r"(b[0]), "r"(b[1]));
}

// -------- scratch (device globals; no allocs) --------
__device__ __nv_bfloat16 g_xh[(size_t)NPIX * 192];
__device__ __nv_bfloat16 g_xl[(size_t)NPIX * 192];
__device__ float g_y1[(size_t)NPIX * 128];
__device__ __nv_bfloat16 g_wt0h[3 * 128 * 64], g_wt0l[3 * 128 * 64];
__device__ __nv_bfloat16 g_wt1h[2 * 128 * 64], g_wt1l[2 * 128 * 64];
__device__ float g_sum0[128], g_ss0[128], g_sum1[128], g_ss1[128];
__device__ float g_a0[128], g_d0[128], g_a1[128], g_d1[128];
__device__ int   g_sel[NPIX * 3];
__device__ float g_coef[NPIX * 3];

__global__ void zero_stats_kernel() {
    int c = threadIdx.x;
    g_sum0[c] = 0.f; g_ss0[c] = 0.f;
    g_sum1[c] = 0.f; g_ss1[c] = 0.f;
}

// -------- grid KNN: first-3-valid in 5x5 window, inverse-distance coefs --------
__global__ void knn_kernel(const float* __restrict__ xyz1,
                           const float* __restrict__ xyz2) {
    int idx = blockIdx.x * blockDim.x + threadIdx.x;
    int b = idx >> 16;
    int n = idx & (NBATCH - 1);
    int h = n >> 10;
    int w = n & (WW_ - 1);

    const float* q = xyz1 + (size_t)idx * 3;
    float qx = q[0], qy = q[1], qz = q[2];

    int   sel[3] = {0, 0, 0};
    float mk[3]  = {0.f, 0.f, 0.f};
    int cnt = 0;

    #pragma unroll
    for (int dh = -2; dh <= 2; dh++) {
        int hh = h + dh;
        if (hh < 0 || hh >= HH_) continue;
        #pragma unroll
        for (int dw = -2; dw <= 2; dw++) {
            int ww = w + dw;
            if (ww < 0 || ww >= WW_) continue;
            int nn = (hh << 10) + ww;
            const float* p = xyz2 + ((size_t)b * NBATCH + nn) * 3;
            float dx = p[0] - qx, dy = p[1] - qy, dz = p[2] - qz;
            float d2 = dx * dx + dy * dy + dz * dz;
            if (d2 < 10000.0f && cnt < 3) { sel[cnt] = nn; mk[cnt] = 1.f; cnt++; }
        }
    }
    float inv[3]; float dsum = 0.f;
    #pragma unroll
    for (int s = 0; s < 3; s++) {
        const float* p = xyz2 + ((size_t)b * NBATCH + sel[s]) * 3;
        float gx = p[0] * mk[s], gy = p[1] * mk[s], gz = p[2] * mk[s];
        float dx = gx - qx, dy = gy - qy, dz = gz - qz;
        float d2 = dx * dx + dy * dy + dz * dz;
        if (d2 < 1e-10f) d2 = 1e-10f;
        inv[s] = 1.0f / d2;
        dsum += inv[s];
    }
    float rnorm = 1.0f / dsum;
    #pragma unroll
    for (int s = 0; s < 3; s++) {
        g_sel[idx * 3 + s]  = b * NBATCH + sel[s];
        g_coef[idx * 3 + s] = inv[s] * rnorm * mk[s];
    }
}

// -------- build x = [feat1 | interp], write bf16 hi/lo split --------
__global__ void buildx_kernel(const float* __restrict__ feat1,
                              const float* __restrict__ feat2) {
    int pix = blockIdx.x;
    int c = threadIdx.x;       // 0..191
    float v;
    if (c < C1_) {
        v = feat1[(size_t)pix * C1_ + c];
    } else {
        int c2 = c - C1_;
        int   s0 = g_sel[pix * 3 + 0], s1 = g_sel[pix * 3 + 1], s2 = g_sel[pix * 3 + 2];
        float c0 = g_coef[pix * 3 + 0], cc1 = g_coef[pix * 3 + 1], cc2 = g_coef[pix * 3 + 2];
        v = c0  * feat2[(size_t)s0 * C2_ + c2]
          + cc1 * feat2[(size_t)s1 * C2_ + c2]
          + cc2 * feat2[(size_t)s2 * C2_ + c2];
    }
    __nv_bfloat16 h = __float2bfloat16(v);
    __nv_bfloat16 l = __float2bfloat16(v - __bfloat162float(h));
    g_xh[(size_t)pix * 192 + c] = h;
    g_xl[(size_t)pix * 192 + c] = l;
}

// -------- prep weights: [K,128] -> chunked n-major [k/64][n][k%64], bf16 split --------
__global__ void prepw_kernel(const float* __restrict__ w,
                             __nv_bfloat16* __restrict__ th,
                             __nv_bfloat16* __restrict__ tl, int K) {
    int t = blockIdx.x * 256 + threadIdx.x;
    if (t >= K * 128) return;
    int k = t >> 7, n = t & 127;
    float v = w[t];
    __nv_bfloat16 h = __float2bfloat16(v);
    __nv_bfloat16 l = __float2bfloat16(v - __bfloat162float(h));
    int o = ((k >> 6) * 128 + n) * 64 + (k & 63);
    th[o] = h; tl[o] = l;
}

// -------- warp-MMA bf16-split GEMM: Y[M,128] = act(A)[M,K] @ W[K,128] + bias --------
// SMEM: Ah[128][72], Al[128][72], Bh[128][72] (n-major), Bl[128][72]
template<int NCH, bool ACT>
__global__ __launch_bounds__(256)
void gemm_mma(const float* __restrict__ Af,
              const __nv_bfloat16* __restrict__ Ah,
              const __nv_bfloat16* __restrict__ Al,
              const __nv_bfloat16* __restrict__ Bh,
              const __nv_bfloat16* __restrict__ Bl,
              const float* __restrict__ bias,
              const float* __restrict__ bna, const float* __restrict__ bnd,
              float* __restrict__ Y) {
    extern __shared__ __nv_bfloat16 sm[];
    __nv_bfloat16* sAh = sm;
    __nv_bfloat16* sAl = sm + 128 * LDS_;
    __nv_bfloat16* sBh = sm + 2 * 128 * LDS_;
    __nv_bfloat16* sBl = sm + 3 * 128 * LDS_;
    const uint32_t sbase = smem_u32(sm);

    const int tid = threadIdx.x, wid = tid >> 5, lane = tid & 31;
    const int m0 = blockIdx.x * 128;
    const int wm = (wid & 3) * 32;       // warp m offset within tile
    const int wn = (wid >> 2) * 64;      // warp n offset
    const int LDA = NCH * 64;

    float acc[2][8][4];
    #pragma unroll
    for (int mi = 0; mi < 2; mi++)
        #pragma unroll
        for (int ni = 0; ni < 8; ni++)
            #pragma unroll
            for (int j = 0; j < 4; j++) acc[mi][ni][j] = 0.f;

    for (int c = 0; c < NCH; c++) {
        if (c) __syncthreads();
        // ---- load A chunk ----
        if (!ACT) {
            #pragma unroll
            for (int i = 0; i < 4; i++) {
                int u = i * 256 + tid;           // 1024 uint4 units
                int row = u >> 3, seg = u & 7;
                size_t go = (size_t)(m0 + row) * LDA + c * 64 + seg * 8;
                *reinterpret_cast<uint4*>(sAh + row * LDS_ + seg * 8) =
                    *reinterpret_cast<const uint4*>(Ah + go);
                *reinterpret_cast<uint4*>(sAl + row * LDS_ + seg * 8) =
                    *reinterpret_cast<const uint4*>(Al + go);
            }
        } else {
            #pragma unroll
            for (int i = 0; i < 8; i++) {
                int u = i * 256 + tid;           // 2048 float4 units
                int row = u >> 4, seg = u & 15;
                float4 v = *reinterpret_cast<const float4*>(
                    Af + (size_t)(m0 + row) * 128 + c * 64 + seg * 4);
                int k = c * 64 + seg * 4;
                v.x = fmaxf(__ldg(bna + k + 0) * v.x + __ldg(bnd + k + 0), 0.f);
                v.y = fmaxf(__ldg(bna + k + 1) * v.y + __ldg(bnd + k + 1), 0.f);
                v.z = fmaxf(__ldg(bna + k + 2) * v.z + __ldg(bnd + k + 2), 0.f);
                v.w = fmaxf(__ldg(bna + k + 3) * v.w + __ldg(bnd + k + 3), 0.f);
                __nv_bfloat16 hx = __float2bfloat16(v.x), hy = __float2bfloat16(v.y);
                __nv_bfloat16 hz = __float2bfloat16(v.z), hw = __float2bfloat16(v.w);
                __nv_bfloat16 lx = __float2bfloat16(v.x - __bfloat162float(hx));
                __nv_bfloat16 ly = __float2bfloat16(v.y - __bfloat162float(hy));
                __nv_bfloat16 lz = __float2bfloat16(v.z - __bfloat162float(hz));
                __nv_bfloat16 lw = __float2bfloat16(v.w - __bfloat162float(hw));
                __nv_bfloat162 h01(hx, hy), h23(hz, hw), l01(lx, ly), l23(lz, lw);
                uint2 hv, lv;
                hv.x = *reinterpret_cast<uint32_t*>(&h01); hv.y = *reinterpret_cast<uint32_t*>(&h23);
                lv.x = *reinterpret_cast<uint32_t*>(&l01); lv.y = *reinterpret_cast<uint32_t*>(&l23);
                *reinterpret_cast<uint2*>(sAh + row * LDS_ + seg * 4) = hv;
                *reinterpret_cast<uint2*>(sAl + row * LDS_ + seg * 4) = lv;
            }
        }
        // ---- load B chunk (pre-transposed n-major: [n][64]) ----
        #pragma unroll
        for (int i = 0; i < 4; i++) {
            int u = i * 256 + tid;               // 1024 uint4 units
            int row = u >> 3, seg = u & 7;
            int go = c * 8192 + row * 64 + seg * 8;
            *reinterpret_cast<uint4*>(sBh + row * LDS_ + seg * 8) =
                *reinterpret_cast<const uint4*>(Bh + go);
            *reinterpret_cast<uint4*>(sBl + row * LDS_ + seg * 8) =
                *reinterpret_cast<const uint4*>(Bl + go);
        }
        __syncthreads();

        // ---- MMA over 4 k16 steps ----
        #pragma unroll
        for (int ks = 0; ks < 4; ks++) {
            uint32_t ah[2][4], al[2][4];
            #pragma unroll
            for (int mi = 0; mi < 2; mi++) {
                int row = wm + mi * 16 + (lane & 15);
                int col = ks * 16 + (lane >> 4) * 8;
                uint32_t off = (uint32_t)(row * LDS_ + col) * 2;
                ldm_x4(ah[mi], sbase + 0 * 128 * LDS_ * 2 + off);
                ldm_x4(al[mi], sbase + 1 * 128 * LDS_ * 2 + off);
            }
            #pragma unroll
            for (int ni = 0; ni < 8; ni++) {
                int row = wn + ni * 8 + (lane & 7);
                int col = ks * 16 + ((lane >> 3) & 1) * 8;
                uint32_t off = (uint32_t)(row * LDS_ + col) * 2;
                uint32_t bh[2], bl[2];
                ldm_x2(bh, sbase + 2 * 128 * LDS_ * 2 + off);
                ldm_x2(bl, sbase + 3 * 128 * LDS_ * 2 + off);
                #pragma unroll
                for (int mi = 0; mi < 2; mi++) {
                    mma_bf16(acc[mi][ni], ah[mi], bh);
                    mma_bf16(acc[mi][ni], ah[mi], bl);
                    mma_bf16(acc[mi][ni], al[mi], bh);
                }
            }
        }
    }

    // ---- epilogue: bias + store ----
    float2 bb[8];
    #pragma unroll
    for (int ni = 0; ni < 8; ni++) {
        int n = wn + ni * 8 + (lane & 3) * 2;
        bb[ni].x = __ldg(bias + n);
        bb[ni].y = __ldg(bias + n + 1);
    }
    #pragma unroll
    for (int mi = 0; mi < 2; mi++) {
        int r0 = m0 + wm + mi * 16 + (lane >> 2);
        #pragma unroll
        for (int ni = 0; ni < 8; ni++) {
            int n = wn + ni * 8 + (lane & 3) * 2;
            float2 v0, v1;
            v0.x = acc[mi][ni][0] + bb[ni].x;
            v0.y = acc[mi][ni][1] + bb[ni].y;
            v1.x = acc[mi][ni][2] + bb[ni].x;
            v1.y = acc[mi][ni][3] + bb[ni].y;
            *reinterpret_cast<float2*>(Y + (size_t)r0 * 128 + n) = v0;
            *reinterpret_cast<float2*>(Y + (size_t)(r0 + 8) * 128 + n) = v1;
        }
    }
}

// -------- per-channel sum / sumsq over [NPIX,128] --------
__global__ __launch_bounds__(256)
void colstats_kernel(const float* __restrict__ Y,
                     float* __restrict__ gsum, float* __restrict__ gss) {
    __shared__ float sS[128], sQ[128];
    int tid = threadIdx.x;
    int col4 = tid & 31, rl = tid >> 5;
    if (tid < 128) { sS[tid] = 0.f; sQ[tid] = 0.f; }
    __syncthreads();
    float4 s = make_float4(0, 0, 0, 0), q = make_float4(0, 0, 0, 0);
    size_t base = (size_t)blockIdx.x * 512 + rl * 64;
    for (int r = 0; r < 64; r++) {
        float4 v = *reinterpret_cast<const float4*>(Y + (base + r) * 128 + col4 * 4);
        s.x += v.x; s.y += v.y; s.z += v.z; s.w += v.w;
        q.x += v.x * v.x; q.y += v.y * v.y; q.z += v.z * v.z; q.w += v.w * v.w;
    }
    atomicAdd(&sS[col4 * 4 + 0], s.x); atomicAdd(&sS[col4 * 4 + 1], s.y);
    atomicAdd(&sS[col4 * 4 + 2], s.z); atomicAdd(&sS[col4 * 4 + 3], s.w);
    atomicAdd(&sQ[col4 * 4 + 0], q.x); atomicAdd(&sQ[col4 * 4 + 1], q.y);
    atomicAdd(&sQ[col4 * 4 + 2], q.z); atomicAdd(&sQ[col4 * 4 + 3], q.w);
    __syncthreads();
    if (tid < 128) {
        atomicAdd(&gsum[tid], sS[tid]);
        atomicAdd(&gss[tid], sQ[tid]);
    }
}

__global__ void finalize_stats(const float* __restrict__ gsum, const float* __restrict__ gss,
                               const float* __restrict__ g, const float* __restrict__ be,
                               float* __restrict__ a, float* __restrict__ d) {
    int c = threadIdx.x;
    float mu  = gsum[c] * INV_M;
    float var = gss[c] * INV_M - mu * mu;
    float s = g[c] * rsqrtf(var + BN_EPS_);
    a[c] = s;
    d[c] = be[c] - mu * s;
}

__global__ void bn_out_kernel(float* __restrict__ out,
                              const float* __restrict__ a, const float* __restrict__ d) {
    int i = blockIdx.x * blockDim.x + threadIdx.x;
    int c = (i * 4) & 127;
    float4 v = reinterpret_cast<float4*>(out)[i];
    v.x = fmaxf(a[c + 0] * v.x + d[c + 0], 0.f);
    v.y = fmaxf(a[c + 1] * v.y + d[c + 1], 0.f);
    v.z = fmaxf(a[c + 2] * v.z + d[c + 2], 0.f);
    v.w = fmaxf(a[c + 3] * v.w + d[c + 3], 0.f);
    reinterpret_cast<float4*>(out)[i] = v;
}

extern "C" void kernel_launch(void* const* d_in, const int* in_sizes, int n_in,
                              void* d_out, int out_size) {
    const float* xyz1  = (const float*)d_in[0];
    const float* xyz2  = (const float*)d_in[1];
    const float* feat1 = (const float*)d_in[2];
    const float* feat2 = (const float*)d_in[3];
    const float* w0    = (const float*)d_in[4];
    const float* b0    = (const float*)d_in[5];
    const float* gg0   = (const float*)d_in[6];
    const float* be0   = (const float*)d_in[7];
    const float* w1    = (const float*)d_in[8];
    const float* b1    = (const float*)d_in[9];
    const float* gg1   = (const float*)d_in[10];
    const float* be1   = (const float*)d_in[11];
    float* out = (float*)d_out;

    float *p_y1, *p_sum0, *p_ss0, *p_sum1, *p_ss1, *p_a0, *p_d0, *p_a1, *p_d1;
    __nv_bfloat16 *p_xh, *p_xl, *p_w0h, *p_w0l, *p_w1h, *p_w1l;
    cudaGetSymbolAddress((void**)&p_y1,   g_y1);
    cudaGetSymbolAddress((void**)&p_xh,   g_xh);
    cudaGetSymbolAddress((void**)&p_xl,   g_xl);
    cudaGetSymbolAddress((void**)&p_w0h,  g_wt0h);
    cudaGetSymbolAddress((void**)&p_w0l,  g_wt0l);
    cudaGetSymbolAddress((void**)&p_w1h,  g_wt1h);
    cudaGetSymbolAddress((void**)&p_w1l,  g_wt1l);
    cudaGetSymbolAddress((void**)&p_sum0, g_sum0);
    cudaGetSymbolAddress((void**)&p_ss0,  g_ss0);
    cudaGetSymbolAddress((void**)&p_sum1, g_sum1);
    cudaGetSymbolAddress((void**)&p_ss1,  g_ss1);
    cudaGetSymbolAddress((void**)&p_a0,   g_a0);
    cudaGetSymbolAddress((void**)&p_d0,   g_d0);
    cudaGetSymbolAddress((void**)&p_a1,   g_a1);
    cudaGetSymbolAddress((void**)&p_d1,   g_d1);

    const int smemB = 4 * 128 * LDS_ * 2;   // 73728 bytes
    cudaFuncSetAttribute(gemm_mma<3, false>, cudaFuncAttributeMaxDynamicSharedMemorySize, smemB);
    cudaFuncSetAttribute(gemm_mma<2, true>,  cudaFuncAttributeMaxDynamicSharedMemorySize, smemB);

    zero_stats_kernel<<<1, 128>>>();
    knn_kernel<<<NPIX / 256, 256>>>(xyz1, xyz2);
    buildx_kernel<<<NPIX, 192>>>(feat1, feat2);
    prepw_kernel<<<(192 * 128 + 255) / 256, 256>>>(w0, p_w0h, p_w0l, 192);
    prepw_kernel<<<(128 * 128 + 255) / 256, 256>>>(w1, p_w1h, p_w1l, 128);

    gemm_mma<3, false><<<NPIX / 128, 256, smemB>>>(
        nullptr, p_xh, p_xl, p_w0h, p_w0l, b0, nullptr, nullptr, p_y1);

    colstats_kernel<<<256, 256>>>(p_y1, p_sum0, p_ss0);
    finalize_stats<<<1, 128>>>(p_sum0, p_ss0, gg0, be0, p_a0, p_d0);

    gemm_mma<2, true><<<NPIX / 128, 256, smemB>>>(
        p_y1, nullptr, nullptr, p_w1h, p_w1l, b1, p_a0, p_d0, out);

    colstats_kernel<<<256, 256>>>(out, p_sum1, p_ss1);
    finalize_stats<<<1, 128>>>(p_sum1, p_ss1, gg1, be1, p_a1, p_d1);

    bn_out_kernel<<<(NPIX * 128 / 4) / 256, 256>>>(out, p_a1, p_d1);
}

// round 10
// speedup vs baseline: 1.4583x; 1.4356x over previous
#include <cuda_runtime.h>
#include <cuda_bf16.h>
#include <cstdint>

#define NPIX   131072          // B*H*W
#define NBATCH 65536           // H*W
#define HH_    64
#define WW_    1024
#define C1_    64
#define C2_    128
#define INV_M  (1.0f/131072.0f)
#define BN_EPS_ 1e-5f

// padded smem tile stride: 64 data + 8 pad elements -> 144B rows (144 = 9*16, 16B-aligned)
#define LDS_   72
#define STAGE_ 73728           // bytes per stage: 4 tiles * 128 * 72 * 2

__device__ __forceinline__ uint32_t smem_u32(const void* p) {
    uint32_t a;
    asm("{ .reg .u64 t; cvta.to.shared.u64 t, %1; cvt.u32.u64 %0, t; }" : "=r"(a) : "l"(p));
    return a;
}
__device__ __forceinline__ void cp16(uint32_t dst, const void* src) {
    asm volatile("cp.async.ca.shared.global [%0], [%1], 16;" :: "r"(dst), "l"(src));
}
#define CP_COMMIT() asm volatile("cp.async.commit_group;" ::: "memory")
#define CP_WAIT0()  asm volatile("cp.async.wait_group 0;" ::: "memory")

__device__ __forceinline__ void ldm_x4(uint32_t* r, uint32_t addr) {
    asm volatile("ldmatrix.sync.aligned.m8n8.x4.shared.b16 {%0,%1,%2,%3}, [%4];"
        : "=r"(r[0]), "=r"(r[1]), "=r"(r[2]), "=r"(r[3]) : "r"(addr));
}
__device__ __forceinline__ void ldm_x2(uint32_t* r, uint32_t addr) {
    asm volatile("ldmatrix.sync.aligned.m8n8.x2.shared.b16 {%0,%1}, [%2];"
        : "=r"(r[0]), "=r"(r[1]) : "r"(addr));
}
__device__ __forceinline__ void mma_bf16(float* c, const uint32_t* a, const uint32_t* b) {
    asm volatile("mma.sync.aligned.m16n8k16.row.col.f32.bf16.bf16.f32 "
        "{%0,%1,%2,%3}, {%4,%5,%6,%7}, {%8,%9}, {%0,%1,%2,%3};"
        : "+f"(c[0]), "+f"(c[1]), "+f"(c[2]), "+f"(c[3])
        : "r"(a[0]), "r"(a[1]), "r"(a[2]), "r"(a[3]), "r"(b[0]), "r"(b[1]));
}

// -------- scratch (device globals; no allocs) --------
__device__ __nv_bfloat16 g_xh[(size_t)NPIX * 192];
__device__ __nv_bfloat16 g_xl[(size_t)NPIX * 192];
__device__ float g_y1[(size_t)NPIX * 128];
__device__ __nv_bfloat16 g_wt0h[3 * 128 * 64], g_wt0l[3 * 128 * 64];
__device__ __nv_bfloat16 g_wt1h[2 * 128 * 64], g_wt1l[2 * 128 * 64];
__device__ float g_sum0[128], g_ss0[128], g_sum1[128], g_ss1[128];
__device__ float g_a0[128], g_d0[128], g_a1[128], g_d1[128];
__device__ int   g_sel[NPIX * 3];
__device__ float g_coef[NPIX * 3];

__global__ void zero_stats_kernel() {
    int c = threadIdx.x;
    g_sum0[c] = 0.f; g_ss0[c] = 0.f;
    g_sum1[c] = 0.f; g_ss1[c] = 0.f;
}

// -------- grid KNN: first-3-valid in 5x5 window, inverse-distance coefs --------
__global__ void knn_kernel(const float* __restrict__ xyz1,
                           const float* __restrict__ xyz2) {
    int idx = blockIdx.x * blockDim.x + threadIdx.x;
    int b = idx >> 16;
    int n = idx & (NBATCH - 1);
    int h = n >> 10;
    int w = n & (WW_ - 1);

    const float* q = xyz1 + (size_t)idx * 3;
    float qx = q[0], qy = q[1], qz = q[2];

    int   sel[3] = {0, 0, 0};
    float mk[3]  = {0.f, 0.f, 0.f};
    int cnt = 0;

    #pragma unroll
    for (int dh = -2; dh <= 2; dh++) {
        int hh = h + dh;
        if (hh < 0 || hh >= HH_) continue;
        #pragma unroll
        for (int dw = -2; dw <= 2; dw++) {
            int ww = w + dw;
            if (ww < 0 || ww >= WW_) continue;
            int nn = (hh << 10) + ww;
            const float* p = xyz2 + ((size_t)b * NBATCH + nn) * 3;
            float dx = p[0] - qx, dy = p[1] - qy, dz = p[2] - qz;
            float d2 = dx * dx + dy * dy + dz * dz;
            if (d2 < 10000.0f && cnt < 3) { sel[cnt] = nn; mk[cnt] = 1.f; cnt++; }
        }
    }
    float inv[3]; float dsum = 0.f;
    #pragma unroll
    for (int s = 0; s < 3; s++) {
        const float* p = xyz2 + ((size_t)b * NBATCH + sel[s]) * 3;
        float gx = p[0] * mk[s], gy = p[1] * mk[s], gz = p[2] * mk[s];
        float dx = gx - qx, dy = gy - qy, dz = gz - qz;
        float d2 = dx * dx + dy * dy + dz * dz;
        if (d2 < 1e-10f) d2 = 1e-10f;
        inv[s] = 1.0f / d2;
        dsum += inv[s];
    }
    float rnorm = 1.0f / dsum;
    #pragma unroll
    for (int s = 0; s < 3; s++) {
        g_sel[idx * 3 + s]  = b * NBATCH + sel[s];
        g_coef[idx * 3 + s] = inv[s] * rnorm * mk[s];
    }
}

// -------- prep weights: [K,128] -> chunked n-major [k/64][n][k%64], bf16 split --------
__global__ void prepw_kernel(const float* __restrict__ w,
                             __nv_bfloat16* __restrict__ th,
                             __nv_bfloat16* __restrict__ tl, int K) {
    int t = blockIdx.x * 256 + threadIdx.x;
    if (t >= K * 128) return;
    int k = t >> 7, n = t & 127;
    float v = w[t];
    __nv_bfloat16 h = __float2bfloat16(v);
    __nv_bfloat16 l = __float2bfloat16(v - __bfloat162float(h));
    int o = ((k >> 6) * 128 + n) * 64 + (k & 63);
    th[o] = h; tl[o] = l;
}

// -------- buildx: warp-per-pixel, coalesced vector loads, bf16 hi/lo split --------
__global__ __launch_bounds__(256)
void buildx_kernel(const float* __restrict__ feat1,
                   const float* __restrict__ feat2) {
    int pix  = blockIdx.x * 8 + (threadIdx.x >> 5);
    int lane = threadIdx.x & 31;

    int   s0 = g_sel[pix * 3 + 0], s1 = g_sel[pix * 3 + 1], s2 = g_sel[pix * 3 + 2];
    float c0 = g_coef[pix * 3 + 0], c1 = g_coef[pix * 3 + 1], c2 = g_coef[pix * 3 + 2];

    // feat1 part: 2 floats per lane (channels lane*2, lane*2+1)
    float2 f = *reinterpret_cast<const float2*>(feat1 + (size_t)pix * 64 + lane * 2);
    {
        __nv_bfloat16 hx = __float2bfloat16(f.x), hy = __float2bfloat16(f.y);
        __nv_bfloat16 lx = __float2bfloat16(f.x - __bfloat162float(hx));
        __nv_bfloat16 ly = __float2bfloat16(f.y - __bfloat162float(hy));
        __nv_bfloat162 hp(hx, hy), lp(lx, ly);
        *reinterpret_cast<__nv_bfloat162*>(g_xh + (size_t)pix * 192 + lane * 2) = hp;
        *reinterpret_cast<__nv_bfloat162*>(g_xl + (size_t)pix * 192 + lane * 2) = lp;
    }

    // interp part: 4 channels per lane
    float4 a = *reinterpret_cast<const float4*>(feat2 + (size_t)s0 * 128 + lane * 4);
    float4 b = *reinterpret_cast<const float4*>(feat2 + (size_t)s1 * 128 + lane * 4);
    float4 c = *reinterpret_cast<const float4*>(feat2 + (size_t)s2 * 128 + lane * 4);
    float v0 = c0 * a.x + c1 * b.x + c2 * c.x;
    float v1 = c0 * a.y + c1 * b.y + c2 * c.y;
    float v2 = c0 * a.z + c1 * b.z + c2 * c.z;
    float v3 = c0 * a.w + c1 * b.w + c2 * c.w;
    __nv_bfloat16 h0 = __float2bfloat16(v0), h1 = __float2bfloat16(v1);
    __nv_bfloat16 h2 = __float2bfloat16(v2), h3 = __float2bfloat16(v3);
    __nv_bfloat16 l0 = __float2bfloat16(v0 - __bfloat162float(h0));
    __nv_bfloat16 l1 = __float2bfloat16(v1 - __bfloat162float(h1));
    __nv_bfloat16 l2 = __float2bfloat16(v2 - __bfloat162float(h2));
    __nv_bfloat16 l3 = __float2bfloat16(v3 - __bfloat162float(h3));
    __nv_bfloat162 h01(h0, h1), h23(h2, h3), l01(l0, l1), l23(l2, l3);
    uint2 hv, lv;
    hv.x = *reinterpret_cast<uint32_t*>(&h01); hv.y = *reinterpret_cast<uint32_t*>(&h23);
    lv.x = *reinterpret_cast<uint32_t*>(&l01); lv.y = *reinterpret_cast<uint32_t*>(&l23);
    *reinterpret_cast<uint2*>(g_xh + (size_t)pix * 192 + 64 + lane * 4) = hv;
    *reinterpret_cast<uint2*>(g_xl + (size_t)pix * 192 + 64 + lane * 4) = lv;
}

// -------- shared MMA-on-chunk + epilogue helpers --------
__device__ __forceinline__ void mma_chunk(uint32_t sb, int lane, int wm, int wn,
                                          float (&acc)[2][8][4]) {
    #pragma unroll
    for (int ks = 0; ks < 4; ks++) {
        uint32_t ah[2][4], al[2][4];
        #pragma unroll
        for (int mi = 0; mi < 2; mi++) {
            int row = wm + mi * 16 + (lane & 15);
            int col = ks * 16 + (lane >> 4) * 8;
            uint32_t off = (uint32_t)(row * LDS_ + col) * 2;
            ldm_x4(ah[mi], sb + off);
            ldm_x4(al[mi], sb + 128 * LDS_ * 2 + off);
        }
        #pragma unroll
        for (int ni = 0; ni < 8; ni++) {
            int row = wn + ni * 8 + (lane & 7);
            int col = ks * 16 + ((lane >> 3) & 1) * 8;
            uint32_t off = (uint32_t)(row * LDS_ + col) * 2;
            uint32_t bh[2], bl[2];
            ldm_x2(bh, sb + 2 * 128 * LDS_ * 2 + off);
            ldm_x2(bl, sb + 3 * 128 * LDS_ * 2 + off);
            #pragma unroll
            for (int mi = 0; mi < 2; mi++) {
                mma_bf16(acc[mi][ni], ah[mi], bh);
                mma_bf16(acc[mi][ni], ah[mi], bl);
                mma_bf16(acc[mi][ni], al[mi], bh);
            }
        }
    }
}

// epilogue: bias add + store + per-channel sum/sumsq (shfl-reduce + global red)
__device__ __forceinline__ void epilogue_stats(float (&acc)[2][8][4],
        const float* __restrict__ bias, float* __restrict__ Y,
        float* __restrict__ gsum, float* __restrict__ gss,
        int m0, int wm, int wn, int lane) {
    float2 bb[8];
    #pragma unroll
    for (int ni = 0; ni < 8; ni++) {
        int n = wn + ni * 8 + (lane & 3) * 2;
        bb[ni].x = __ldg(bias + n);
        bb[ni].y = __ldg(bias + n + 1);
    }
    float s[16], q[16];
    #pragma unroll
    for (int t = 0; t < 16; t++) { s[t] = 0.f; q[t] = 0.f; }

    #pragma unroll
    for (int mi = 0; mi < 2; mi++) {
        int r0 = m0 + wm + mi * 16 + (lane >> 2);
        #pragma unroll
        for (int ni = 0; ni < 8; ni++) {
            int n = wn + ni * 8 + (lane & 3) * 2;
            float v0 = acc[mi][ni][0] + bb[ni].x;
            float v1 = acc[mi][ni][1] + bb[ni].y;
            float v2 = acc[mi][ni][2] + bb[ni].x;
            float v3 = acc[mi][ni][3] + bb[ni].y;
            *reinterpret_cast<float2*>(Y + (size_t)r0 * 128 + n) = make_float2(v0, v1);
            *reinterpret_cast<float2*>(Y + (size_t)(r0 + 8) * 128 + n) = make_float2(v2, v3);
            s[ni * 2 + 0] += v0 + v2;          s[ni * 2 + 1] += v1 + v3;
            q[ni * 2 + 0] += v0 * v0 + v2 * v2; q[ni * 2 + 1] += v1 * v1 + v3 * v3;
        }
    }
    // reduce across row-lane groups (lanes differing in bits 2..4; preserves lane&3)
    #pragma unroll
    for (int t = 0; t < 16; t++) {
        #pragma unroll
        for (int o = 4; o < 32; o <<= 1) {
            s[t] += __shfl_xor_sync(0xffffffffu, s[t], o);
            q[t] += __shfl_xor_sync(0xffffffffu, q[t], o);
        }
    }
    if (lane < 4) {
        #pragma unroll
        for (int ni = 0; ni < 8; ni++) {
            int col = wn + ni * 8 + lane * 2;
            atomicAdd(gsum + col,     s[ni * 2 + 0]);
            atomicAdd(gsum + col + 1, s[ni * 2 + 1]);
            atomicAdd(gss  + col,     q[ni * 2 + 0]);
            atomicAdd(gss  + col + 1, q[ni * 2 + 1]);
        }
    }
}

// -------- GEMM1: bf16-split, cp.async double-buffered, fused stats --------
template<int NCH>
__global__ __launch_bounds__(256)
void gemm1_mma(const __nv_bfloat16* __restrict__ Ah,
               const __nv_bfloat16* __restrict__ Al,
               const __nv_bfloat16* __restrict__ Bh,
               const __nv_bfloat16* __restrict__ Bl,
               const float* __restrict__ bias,
               float* __restrict__ Y,
               float* __restrict__ gsum, float* __restrict__ gss) {
    extern __shared__ __align__(16) __nv_bfloat16 smg[];
    const uint32_t sbase = smem_u32(smg);
    const int tid = threadIdx.x, lane = tid & 31, wid = tid >> 5;
    const int m0 = blockIdx.x * 128;
    const int wm = (wid & 3) * 32, wn = (wid >> 2) * 64;
    const int LDA = NCH * 64;

    float acc[2][8][4];
    #pragma unroll
    for (int mi = 0; mi < 2; mi++)
        #pragma unroll
        for (int ni = 0; ni < 8; ni++)
            #pragma unroll
            for (int j = 0; j < 4; j++) acc[mi][ni][j] = 0.f;

    auto loadc = [&](int c, int stg) {
        uint32_t sb = sbase + stg * STAGE_;
        #pragma unroll
        for (int i = 0; i < 4; i++) {
            int u = i * 256 + tid, row = u >> 3, seg = u & 7;
            size_t go = (size_t)(m0 + row) * LDA + c * 64 + seg * 8;
            uint32_t so = (uint32_t)(row * LDS_ + seg * 8) * 2;
            cp16(sb + so, Ah + go);
            cp16(sb + 128 * LDS_ * 2 + so, Al + go);
            int gb = c * 8192 + row * 64 + seg * 8;
            cp16(sb + 2 * 128 * LDS_ * 2 + so, Bh + gb);
            cp16(sb + 3 * 128 * LDS_ * 2 + so, Bl + gb);
        }
        CP_COMMIT();
    };

    loadc(0, 0);
    CP_WAIT0(); __syncthreads();
    #pragma unroll
    for (int c = 0; c < NCH; c++) {
        if (c + 1 < NCH) loadc(c + 1, (c + 1) & 1);
        mma_chunk(sbase + (c & 1) * STAGE_, lane, wm, wn, acc);
        if (c + 1 < NCH) { CP_WAIT0(); __syncthreads(); }
    }
    epilogue_stats(acc, bias, Y, gsum, gss, m0, wm, wn, lane);
}

// -------- GEMM2: fp32 A with fused BN+ReLU+split, pipelined, fused stats --------
__global__ __launch_bounds__(256)
void gemm2_mma(const float* __restrict__ Af,
               const __nv_bfloat16* __restrict__ Bh,
               const __nv_bfloat16* __restrict__ Bl,
               const float* __restrict__ bias,
               const float* __restrict__ bna, const float* __restrict__ bnd,
               float* __restrict__ Y,
               float* __restrict__ gsum, float* __restrict__ gss) {
    extern __shared__ __align__(16) __nv_bfloat16 smg[];
    const uint32_t sbase = smem_u32(smg);
    const int tid = threadIdx.x, lane = tid & 31, wid = tid >> 5;
    const int m0 = blockIdx.x * 128;
    const int wm = (wid & 3) * 32, wn = (wid >> 2) * 64;

    float acc[2][8][4];
    #pragma unroll
    for (int mi = 0; mi < 2; mi++)
        #pragma unroll
        for (int ni = 0; ni < 8; ni++)
            #pragma unroll
            for (int j = 0; j < 4; j++) acc[mi][ni][j] = 0.f;

    auto cvt_store = [&](float4 v, int c, int row, int seg, uint32_t sb) {
        int k = c * 64 + seg * 4;
        v.x = fmaxf(__ldg(bna + k + 0) * v.x + __ldg(bnd + k + 0), 0.f);
        v.y = fmaxf(__ldg(bna + k + 1) * v.y + __ldg(bnd + k + 1), 0.f);
        v.z = fmaxf(__ldg(bna + k + 2) * v.z + __ldg(bnd + k + 2), 0.f);
        v.w = fmaxf(__ldg(bna + k + 3) * v.w + __ldg(bnd + k + 3), 0.f);
        __nv_bfloat16 hx = __float2bfloat16(v.x), hy = __float2bfloat16(v.y);
        __nv_bfloat16 hz = __float2bfloat16(v.z), hw = __float2bfloat16(v.w);
        __nv_bfloat16 lx = __float2bfloat16(v.x - __bfloat162float(hx));
        __nv_bfloat16 ly = __float2bfloat16(v.y - __bfloat162float(hy));
        __nv_bfloat16 lz = __float2bfloat16(v.z - __bfloat162float(hz));
        __nv_bfloat16 lw = __float2bfloat16(v.w - __bfloat162float(hw));
        __nv_bfloat162 h01(hx, hy), h23(hz, hw), l01(lx, ly), l23(lz, lw);
        uint2 hv, lv;
        hv.x = *reinterpret_cast<uint32_t*>(&h01); hv.y = *reinterpret_cast<uint32_t*>(&h23);
        lv.x = *reinterpret_cast<uint32_t*>(&l01); lv.y = *reinterpret_cast<uint32_t*>(&l23);
        uint32_t so = (uint32_t)(row * LDS_ + seg * 4) * 2;
        *reinterpret_cast<uint2*>((char*)smg + (sb - sbase) + so) = hv;
        *reinterpret_cast<uint2*>((char*)smg + (sb - sbase) + 128 * LDS_ * 2 + so) = lv;
    };
    auto loadB = [&](int c, int stg) {
        uint32_t sb = sbase + stg * STAGE_;
        #pragma unroll
        for (int i = 0; i < 4; i++) {
            int u = i * 256 + tid, row = u >> 3, seg = u & 7;
            uint32_t so = (uint32_t)(row * LDS_ + seg * 8) * 2;
            int gb = c * 8192 + row * 64 + seg * 8;
            cp16(sb + 2 * 128 * LDS_ * 2 + so, Bh + gb);
            cp16(sb + 3 * 128 * LDS_ * 2 + so, Bl + gb);
        }
        CP_COMMIT();
    };

    // chunk 0: convert+store A, async B
    #pragma unroll
    for (int i = 0; i < 8; i++) {
        int u = i * 256 + tid, row = u >> 4, seg = u & 15;
        float4 v = *reinterpret_cast<const float4*>(Af + (size_t)(m0 + row) * 128 + seg * 4);
        cvt_store(v, 0, row, seg, sbase);
    }
    loadB(0, 0);
    // prefetch chunk-1 A raw + async B chunk 1
    float4 pre[8];
    #pragma unroll
    for (int i = 0; i < 8; i++) {
        int u = i * 256 + tid, row = u >> 4, seg = u & 15;
        pre[i] = *reinterpret_cast<const float4*>(Af + (size_t)(m0 + row) * 128 + 64 + seg * 4);
    }
    loadB(1, 1);
    CP_WAIT0(); __syncthreads();

    mma_chunk(sbase, lane, wm, wn, acc);

    #pragma unroll
    for (int i = 0; i < 8; i++) {
        int u = i * 256 + tid, row = u >> 4, seg = u & 15;
        cvt_store(pre[i], 1, row, seg, sbase + STAGE_);
    }
    __syncthreads();

    mma_chunk(sbase + STAGE_, lane, wm, wn, acc);

    epilogue_stats(acc, bias, Y, gsum, gss, m0, wm, wn, lane);
}

__global__ void finalize_stats(const float* __restrict__ gsum, const float* __restrict__ gss,
                               const float* __restrict__ g, const float* __restrict__ be,
                               float* __restrict__ a, float* __restrict__ d) {
    int c = threadIdx.x;
    float mu  = gsum[c] * INV_M;
    float var = gss[c] * INV_M - mu * mu;
    float s = g[c] * rsqrtf(var + BN_EPS_);
    a[c] = s;
    d[c] = be[c] - mu * s;
}

__global__ void bn_out_kernel(float* __restrict__ out,
                              const float* __restrict__ a, const float* __restrict__ d) {
    int i = blockIdx.x * blockDim.x + threadIdx.x;
    int c = (i * 4) & 127;
    float4 v = reinterpret_cast<float4*>(out)[i];
    v.x = fmaxf(a[c + 0] * v.x + d[c + 0], 0.f);
    v.y = fmaxf(a[c + 1] * v.y + d[c + 1], 0.f);
    v.z = fmaxf(a[c + 2] * v.z + d[c + 2], 0.f);
    v.w = fmaxf(a[c + 3] * v.w + d[c + 3], 0.f);
    reinterpret_cast<float4*>(out)[i] = v;
}

extern "C" void kernel_launch(void* const* d_in, const int* in_sizes, int n_in,
                              void* d_out, int out_size) {
    const float* xyz1  = (const float*)d_in[0];
    const float* xyz2  = (const float*)d_in[1];
    const float* feat1 = (const float*)d_in[2];
    const float* feat2 = (const float*)d_in[3];
    const float* w0    = (const float*)d_in[4];
    const float* b0    = (const float*)d_in[5];
    const float* gg0   = (const float*)d_in[6];
    const float* be0   = (const float*)d_in[7];
    const float* w1    = (const float*)d_in[8];
    const float* b1    = (const float*)d_in[9];
    const float* gg1   = (const float*)d_in[10];
    const float* be1   = (const float*)d_in[11];
    float* out = (float*)d_out;

    float *p_y1, *p_sum0, *p_ss0, *p_sum1, *p_ss1, *p_a0, *p_d0, *p_a1, *p_d1;
    __nv_bfloat16 *p_xh, *p_xl, *p_w0h, *p_w0l, *p_w1h, *p_w1l;
    cudaGetSymbolAddress((void**)&p_y1,   g_y1);
    cudaGetSymbolAddress((void**)&p_xh,   g_xh);
    cudaGetSymbolAddress((void**)&p_xl,   g_xl);
    cudaGetSymbolAddress((void**)&p_w0h,  g_wt0h);
    cudaGetSymbolAddress((void**)&p_w0l,  g_wt0l);
    cudaGetSymbolAddress((void**)&p_w1h,  g_wt1h);
    cudaGetSymbolAddress((void**)&p_w1l,  g_wt1l);
    cudaGetSymbolAddress((void**)&p_sum0, g_sum0);
    cudaGetSymbolAddress((void**)&p_ss0,  g_ss0);
    cudaGetSymbolAddress((void**)&p_sum1, g_sum1);
    cudaGetSymbolAddress((void**)&p_ss1,  g_ss1);
    cudaGetSymbolAddress((void**)&p_a0,   g_a0);
    cudaGetSymbolAddress((void**)&p_d0,   g_d0);
    cudaGetSymbolAddress((void**)&p_a1,   g_a1);
    cudaGetSymbolAddress((void**)&p_d1,   g_d1);

    const int smemS = 2 * STAGE_;   // 147456 bytes
    cudaFuncSetAttribute(gemm1_mma<3>, cudaFuncAttributeMaxDynamicSharedMemorySize, smemS);
    cudaFuncSetAttribute(gemm2_mma,    cudaFuncAttributeMaxDynamicSharedMemorySize, smemS);

    zero_stats_kernel<<<1, 128>>>();
    knn_kernel<<<NPIX / 256, 256>>>(xyz1, xyz2);
    prepw_kernel<<<(192 * 128 + 255) / 256, 256>>>(w0, p_w0h, p_w0l, 192);
    prepw_kernel<<<(128 * 128 + 255) / 256, 256>>>(w1, p_w1h, p_w1l, 128);
    buildx_kernel<<<NPIX / 8, 256>>>(feat1, feat2);

    gemm1_mma<3><<<NPIX / 128, 256, smemS>>>(
        p_xh, p_xl, p_w0h, p_w0l, b0, p_y1, p_sum0, p_ss0);
    finalize_stats<<<1, 128>>>(p_sum0, p_ss0, gg0, be0, p_a0, p_d0);

    gemm2_mma<<<NPIX / 128, 256, smemS>>>(
        p_y1, p_w1h, p_w1l, b1, p_a0, p_d0, out, p_sum1, p_ss1);
    finalize_stats<<<1, 128>>>(p_sum1, p_ss1, gg1, be1, p_a1, p_d1);

    bn_out_kernel<<<(NPIX * 128 / 4) / 256, 256>>>(out, p_a1, p_d1);
}

// round 11
// speedup vs baseline: 1.5443x; 1.0590x over previous
#include <cuda_runtime.h>
#include <cuda_bf16.h>
#include <cstdint>

#define NPIX   131072          // B*H*W
#define NBATCH 65536           // H*W
#define HH_    64
#define WW_    1024
#define C1_    64
#define C2_    128
#define INV_M  (1.0f/131072.0f)
#define BN_EPS_ 1e-5f

// padded smem tile stride: 64 data + 8 pad elements -> 144B rows
#define LDS_   72
#define STAGE_ 73728           // bytes per stage: 4 tiles * 128 * 72 * 2

__device__ __forceinline__ uint32_t smem_u32(const void* p) {
    uint32_t a;
    asm("{ .reg .u64 t; cvta.to.shared.u64 t, %1; cvt.u32.u64 %0, t; }" : "=r"(a) : "l"(p));
    return a;
}
__device__ __forceinline__ void cp16(uint32_t dst, const void* src) {
    asm volatile("cp.async.ca.shared.global [%0], [%1], 16;" :: "r"(dst), "l"(src));
}
#define CP_COMMIT() asm volatile("cp.async.commit_group;" ::: "memory")
#define CP_WAIT0()  asm volatile("cp.async.wait_group 0;" ::: "memory")

__device__ __forceinline__ void ldm_x4(uint32_t* r, uint32_t addr) {
    asm volatile("ldmatrix.sync.aligned.m8n8.x4.shared.b16 {%0,%1,%2,%3}, [%4];"
        : "=r"(r[0]), "=r"(r[1]), "=r"(r[2]), "=r"(r[3]) : "r"(addr));
}
__device__ __forceinline__ void ldm_x2(uint32_t* r, uint32_t addr) {
    asm volatile("ldmatrix.sync.aligned.m8n8.x2.shared.b16 {%0,%1}, [%2];"
        : "=r"(r[0]), "=r"(r[1]) : "r"(addr));
}
__device__ __forceinline__ void mma_bf16(float* c, const uint32_t* a, const uint32_t* b) {
    asm volatile("mma.sync.aligned.m16n8k16.row.col.f32.bf16.bf16.f32 "
        "{%0,%1,%2,%3}, {%4,%5,%6,%7}, {%8,%9}, {%0,%1,%2,%3};"
        : "+f"(c[0]), "+f"(c[1]), "+f"(c[2]), "+f"(c[3])
        : "r"(a[0]), "r"(a[1]), "r"(a[2]), "r"(a[3]), "r"(b[0]), "r"(b[1]));
}

// -------- scratch (device globals; no allocs) --------
__device__ float g_y1[(size_t)NPIX * 128];
__device__ __nv_bfloat16 g_wt0h[3 * 128 * 64], g_wt0l[3 * 128 * 64];
__device__ __nv_bfloat16 g_wt1h[2 * 128 * 64], g_wt1l[2 * 128 * 64];
__device__ float g_sum0[128], g_ss0[128], g_sum1[128], g_ss1[128];
__device__ float g_a0[128], g_d0[128], g_a1[128], g_d1[128];
__device__ int   g_sel[NPIX * 3];
__device__ float g_coef[NPIX * 3];

__global__ void zero_stats_kernel() {
    int c = threadIdx.x;
    g_sum0[c] = 0.f; g_ss0[c] = 0.f;
    g_sum1[c] = 0.f; g_ss1[c] = 0.f;
}

// -------- grid KNN: first-3-valid in 5x5 window, inverse-distance coefs --------
__global__ void knn_kernel(const float* __restrict__ xyz1,
                           const float* __restrict__ xyz2) {
    int idx = blockIdx.x * blockDim.x + threadIdx.x;
    int b = idx >> 16;
    int n = idx & (NBATCH - 1);
    int h = n >> 10;
    int w = n & (WW_ - 1);

    const float* q = xyz1 + (size_t)idx * 3;
    float qx = q[0], qy = q[1], qz = q[2];

    int   sel[3] = {0, 0, 0};
    float mk[3]  = {0.f, 0.f, 0.f};
    int cnt = 0;

    #pragma unroll
    for (int dh = -2; dh <= 2; dh++) {
        int hh = h + dh;
        if (hh < 0 || hh >= HH_) continue;
        #pragma unroll
        for (int dw = -2; dw <= 2; dw++) {
            int ww = w + dw;
            if (ww < 0 || ww >= WW_) continue;
            int nn = (hh << 10) + ww;
            const float* p = xyz2 + ((size_t)b * NBATCH + nn) * 3;
            float dx = p[0] - qx, dy = p[1] - qy, dz = p[2] - qz;
            float d2 = dx * dx + dy * dy + dz * dz;
            if (d2 < 10000.0f && cnt < 3) { sel[cnt] = nn; mk[cnt] = 1.f; cnt++; }
        }
    }
    float inv[3]; float dsum = 0.f;
    #pragma unroll
    for (int s = 0; s < 3; s++) {
        const float* p = xyz2 + ((size_t)b * NBATCH + sel[s]) * 3;
        float gx = p[0] * mk[s], gy = p[1] * mk[s], gz = p[2] * mk[s];
        float dx = gx - qx, dy = gy - qy, dz = gz - qz;
        float d2 = dx * dx + dy * dy + dz * dz;
        if (d2 < 1e-10f) d2 = 1e-10f;
        inv[s] = 1.0f / d2;
        dsum += inv[s];
    }
    float rnorm = 1.0f / dsum;
    #pragma unroll
    for (int s = 0; s < 3; s++) {
        g_sel[idx * 3 + s]  = b * NBATCH + sel[s];
        g_coef[idx * 3 + s] = inv[s] * rnorm * mk[s];
    }
}

// -------- prep weights: [K,128] -> chunked n-major [k/64][n][k%64], bf16 split --------
__global__ void prepw_kernel(const float* __restrict__ w,
                             __nv_bfloat16* __restrict__ th,
                             __nv_bfloat16* __restrict__ tl, int K) {
    int t = blockIdx.x * 256 + threadIdx.x;
    if (t >= K * 128) return;
    int k = t >> 7, n = t & 127;
    float v = w[t];
    __nv_bfloat16 h = __float2bfloat16(v);
    __nv_bfloat16 l = __float2bfloat16(v - __bfloat162float(h));
    int o = ((k >> 6) * 128 + n) * 64 + (k & 63);
    th[o] = h; tl[o] = l;
}

// -------- shared MMA-on-chunk + epilogue helpers --------
__device__ __forceinline__ void mma_chunk(uint32_t sb, int lane, int wm, int wn,
                                          float (&acc)[2][8][4]) {
    #pragma unroll
    for (int ks = 0; ks < 4; ks++) {
        uint32_t ah[2][4], al[2][4];
        #pragma unroll
        for (int mi = 0; mi < 2; mi++) {
            int row = wm + mi * 16 + (lane & 15);
            int col = ks * 16 + (lane >> 4) * 8;
            uint32_t off = (uint32_t)(row * LDS_ + col) * 2;
            ldm_x4(ah[mi], sb + off);
            ldm_x4(al[mi], sb + 128 * LDS_ * 2 + off);
        }
        #pragma unroll
        for (int ni = 0; ni < 8; ni++) {
            int row = wn + ni * 8 + (lane & 7);
            int col = ks * 16 + ((lane >> 3) & 1) * 8;
            uint32_t off = (uint32_t)(row * LDS_ + col) * 2;
            uint32_t bh[2], bl[2];
            ldm_x2(bh, sb + 2 * 128 * LDS_ * 2 + off);
            ldm_x2(bl, sb + 3 * 128 * LDS_ * 2 + off);
            #pragma unroll
            for (int mi = 0; mi < 2; mi++) {
                mma_bf16(acc[mi][ni], ah[mi], bh);
                mma_bf16(acc[mi][ni], ah[mi], bl);
                mma_bf16(acc[mi][ni], al[mi], bh);
            }
        }
    }
}

// epilogue: bias add + store + per-channel sum/sumsq (shfl-reduce + global red)
__device__ __forceinline__ void epilogue_stats(float (&acc)[2][8][4],
        const float* __restrict__ bias, float* __restrict__ Y,
        float* __restrict__ gsum, float* __restrict__ gss,
        int m0, int wm, int wn, int lane) {
    float2 bb[8];
    #pragma unroll
    for (int ni = 0; ni < 8; ni++) {
        int n = wn + ni * 8 + (lane & 3) * 2;
        bb[ni].x = __ldg(bias + n);
        bb[ni].y = __ldg(bias + n + 1);
    }
    float s[16], q[16];
    #pragma unroll
    for (int t = 0; t < 16; t++) { s[t] = 0.f; q[t] = 0.f; }

    #pragma unroll
    for (int mi = 0; mi < 2; mi++) {
        int r0 = m0 + wm + mi * 16 + (lane >> 2);
        #pragma unroll
        for (int ni = 0; ni < 8; ni++) {
            int n = wn + ni * 8 + (lane & 3) * 2;
            float v0 = acc[mi][ni][0] + bb[ni].x;
            float v1 = acc[mi][ni][1] + bb[ni].y;
            float v2 = acc[mi][ni][2] + bb[ni].x;
            float v3 = acc[mi][ni][3] + bb[ni].y;
            *reinterpret_cast<float2*>(Y + (size_t)r0 * 128 + n) = make_float2(v0, v1);
            *reinterpret_cast<float2*>(Y + (size_t)(r0 + 8) * 128 + n) = make_float2(v2, v3);
            s[ni * 2 + 0] += v0 + v2;          s[ni * 2 + 1] += v1 + v3;
            q[ni * 2 + 0] += v0 * v0 + v2 * v2; q[ni * 2 + 1] += v1 * v1 + v3 * v3;
        }
    }
    #pragma unroll
    for (int t = 0; t < 16; t++) {
        #pragma unroll
        for (int o = 4; o < 32; o <<= 1) {
            s[t] += __shfl_xor_sync(0xffffffffu, s[t], o);
            q[t] += __shfl_xor_sync(0xffffffffu, q[t], o);
        }
    }
    if (lane < 4) {
        #pragma unroll
        for (int ni = 0; ni < 8; ni++) {
            int col = wn + ni * 8 + lane * 2;
            atomicAdd(gsum + col,     s[ni * 2 + 0]);
            atomicAdd(gsum + col + 1, s[ni * 2 + 1]);
            atomicAdd(gss  + col,     q[ni * 2 + 0]);
            atomicAdd(gss  + col + 1, q[ni * 2 + 1]);
        }
    }
}

// split fp32 float4 -> hi/lo bf16, store to stage A region
__device__ __forceinline__ void splitA(const float4& v, char* smg, int stg,
                                       int row, int seg) {
    __nv_bfloat16 hx = __float2bfloat16(v.x), hy = __float2bfloat16(v.y);
    __nv_bfloat16 hz = __float2bfloat16(v.z), hw = __float2bfloat16(v.w);
    __nv_bfloat16 lx = __float2bfloat16(v.x - __bfloat162float(hx));
    __nv_bfloat16 ly = __float2bfloat16(v.y - __bfloat162float(hy));
    __nv_bfloat16 lz = __float2bfloat16(v.z - __bfloat162float(hz));
    __nv_bfloat16 lw = __float2bfloat16(v.w - __bfloat162float(hw));
    __nv_bfloat162 h01(hx, hy), h23(hz, hw), l01(lx, ly), l23(lz, lw);
    uint2 hv, lv;
    hv.x = *reinterpret_cast<uint32_t*>(&h01); hv.y = *reinterpret_cast<uint32_t*>(&h23);
    lv.x = *reinterpret_cast<uint32_t*>(&l01); lv.y = *reinterpret_cast<uint32_t*>(&l23);
    uint32_t so = (uint32_t)(row * LDS_ + seg * 4) * 2;
    *reinterpret_cast<uint2*>(smg + stg * STAGE_ + so) = hv;
    *reinterpret_cast<uint2*>(smg + stg * STAGE_ + 128 * LDS_ * 2 + so) = lv;
}

// -------- GEMM1 with fused gather/interp/concat A-build + fused stats --------
__global__ __launch_bounds__(256)
void gemm1_fused(const float* __restrict__ feat1,
                 const float* __restrict__ feat2,
                 const __nv_bfloat16* __restrict__ Bh,
                 const __nv_bfloat16* __restrict__ Bl,
                 const float* __restrict__ bias,
                 float* __restrict__ Y,
                 float* __restrict__ gsum, float* __restrict__ gss) {
    extern __shared__ __align__(16) char smg[];
    const uint32_t sbase = smem_u32(smg);
    int*   ssel  = reinterpret_cast<int*>(smg + 2 * STAGE_);
    float* scoef = reinterpret_cast<float*>(smg + 2 * STAGE_ + 1536);
    const int tid = threadIdx.x, lane = tid & 31, wid = tid >> 5;
    const int m0 = blockIdx.x * 128;
    const int wm = (wid & 3) * 32, wn = (wid >> 2) * 64;

    float acc[2][8][4];
    #pragma unroll
    for (int mi = 0; mi < 2; mi++)
        #pragma unroll
        for (int ni = 0; ni < 8; ni++)
            #pragma unroll
            for (int j = 0; j < 4; j++) acc[mi][ni][j] = 0.f;

    auto loadB = [&](int c, int stg) {
        uint32_t sb = sbase + stg * STAGE_;
        #pragma unroll
        for (int i = 0; i < 4; i++) {
            int u = i * 256 + tid, row = u >> 3, seg = u & 7;
            uint32_t so = (uint32_t)(row * LDS_ + seg * 8) * 2;
            int gb = c * 8192 + row * 64 + seg * 8;
            cp16(sb + 2 * 128 * LDS_ * 2 + so, Bh + gb);
            cp16(sb + 3 * 128 * LDS_ * 2 + so, Bl + gb);
        }
        CP_COMMIT();
    };
    auto gather = [&](int row, int seg, int half) -> float4 {
        int   s0 = ssel[row * 3 + 0], s1 = ssel[row * 3 + 1], s2 = ssel[row * 3 + 2];
        float c0 = scoef[row * 3 + 0], c1 = scoef[row * 3 + 1], c2 = scoef[row * 3 + 2];
        int off = half * 64 + seg * 4;
        float4 a = *reinterpret_cast<const float4*>(feat2 + (size_t)s0 * 128 + off);
        float4 b = *reinterpret_cast<const float4*>(feat2 + (size_t)s1 * 128 + off);
        float4 c = *reinterpret_cast<const float4*>(feat2 + (size_t)s2 * 128 + off);
        float4 r;
        r.x = c0 * a.x + c1 * b.x + c2 * c.x;
        r.y = c0 * a.y + c1 * b.y + c2 * c.y;
        r.z = c0 * a.z + c1 * b.z + c2 * c.z;
        r.w = c0 * a.w + c1 * b.w + c2 * c.w;
        return r;
    };

    // stage sel/coef for the block's 128 pixels
    for (int t = tid; t < 384; t += 256) {
        ssel[t]  = g_sel[(size_t)m0 * 3 + t];
        scoef[t] = g_coef[(size_t)m0 * 3 + t];
    }

    // chunk 0 A = feat1 (direct)
    #pragma unroll
    for (int i = 0; i < 8; i++) {
        int u = i * 256 + tid, row = u >> 4, seg = u & 15;
        float4 v = *reinterpret_cast<const float4*>(
            feat1 + (size_t)(m0 + row) * 64 + seg * 4);
        splitA(v, smg, 0, row, seg);
    }
    loadB(0, 0);
    __syncthreads();   // sel/coef visible; A s0 stored

    // prefetch chunk-1 interp (feat2 ch 0-63)
    float4 pre[8];
    #pragma unroll
    for (int i = 0; i < 8; i++) {
        int u = i * 256 + tid, row = u >> 4, seg = u & 15;
        pre[i] = gather(row, seg, 0);
    }
    loadB(1, 1);
    CP_WAIT0(); __syncthreads();

    mma_chunk(sbase, lane, wm, wn, acc);              // chunk 0

    #pragma unroll
    for (int i = 0; i < 8; i++) {
        int u = i * 256 + tid, row = u >> 4, seg = u & 15;
        splitA(pre[i], smg, 1, row, seg);
        pre[i] = gather(row, seg, 1);                 // prefetch chunk-2 interp
    }
    __syncthreads();                                  // all past mma(s0); A s1 ready
    loadB(2, 0);                                      // overwrite s0 B

    mma_chunk(sbase + STAGE_, lane, wm, wn, acc);     // chunk 1

    CP_WAIT0();
    #pragma unroll
    for (int i = 0; i < 8; i++) {
        int u = i * 256 + tid, row = u >> 4, seg = u & 15;
        splitA(pre[i], smg, 0, row, seg);
    }
    __syncthreads();

    mma_chunk(sbase, lane, wm, wn, acc);              // chunk 2

    epilogue_stats(acc, bias, Y, gsum, gss, m0, wm, wn, lane);
}

// -------- GEMM2: fp32 A with fused BN+ReLU+split, pipelined, fused stats --------
__global__ __launch_bounds__(256)
void gemm2_mma(const float* __restrict__ Af,
               const __nv_bfloat16* __restrict__ Bh,
               const __nv_bfloat16* __restrict__ Bl,
               const float* __restrict__ bias,
               const float* __restrict__ bna, const float* __restrict__ bnd,
               float* __restrict__ Y,
               float* __restrict__ gsum, float* __restrict__ gss) {
    extern __shared__ __align__(16) char smg[];
    const uint32_t sbase = smem_u32(smg);
    const int tid = threadIdx.x, lane = tid & 31, wid = tid >> 5;
    const int m0 = blockIdx.x * 128;
    const int wm = (wid & 3) * 32, wn = (wid >> 2) * 64;

    float acc[2][8][4];
    #pragma unroll
    for (int mi = 0; mi < 2; mi++)
        #pragma unroll
        for (int ni = 0; ni < 8; ni++)
            #pragma unroll
            for (int j = 0; j < 4; j++) acc[mi][ni][j] = 0.f;

    auto bnrelu = [&](float4 v, int c, int seg) -> float4 {
        int k = c * 64 + seg * 4;
        v.x = fmaxf(__ldg(bna + k + 0) * v.x + __ldg(bnd + k + 0), 0.f);
        v.y = fmaxf(__ldg(bna + k + 1) * v.y + __ldg(bnd + k + 1), 0.f);
        v.z = fmaxf(__ldg(bna + k + 2) * v.z + __ldg(bnd + k + 2), 0.f);
        v.w = fmaxf(__ldg(bna + k + 3) * v.w + __ldg(bnd + k + 3), 0.f);
        return v;
    };
    auto loadB = [&](int c, int stg) {
        uint32_t sb = sbase + stg * STAGE_;
        #pragma unroll
        for (int i = 0; i < 4; i++) {
            int u = i * 256 + tid, row = u >> 3, seg = u & 7;
            uint32_t so = (uint32_t)(row * LDS_ + seg * 8) * 2;
            int gb = c * 8192 + row * 64 + seg * 8;
            cp16(sb + 2 * 128 * LDS_ * 2 + so, Bh + gb);
            cp16(sb + 3 * 128 * LDS_ * 2 + so, Bl + gb);
        }
        CP_COMMIT();
    };

    #pragma unroll
    for (int i = 0; i < 8; i++) {
        int u = i * 256 + tid, row = u >> 4, seg = u & 15;
        float4 v = *reinterpret_cast<const float4*>(Af + (size_t)(m0 + row) * 128 + seg * 4);
        splitA(bnrelu(v, 0, seg), smg, 0, row, seg);
    }
    loadB(0, 0);
    float4 pre[8];
    #pragma unroll
    for (int i = 0; i < 8; i++) {
        int u = i * 256 + tid, row = u >> 4, seg = u & 15;
        pre[i] = *reinterpret_cast<const float4*>(Af + (size_t)(m0 + row) * 128 + 64 + seg * 4);
    }
    loadB(1, 1);
    CP_WAIT0(); __syncthreads();

    mma_chunk(sbase, lane, wm, wn, acc);

    #pragma unroll
    for (int i = 0; i < 8; i++) {
        int u = i * 256 + tid, row = u >> 4, seg = u & 15;
        splitA(bnrelu(pre[i], 1, seg), smg, 1, row, seg);
    }
    __syncthreads();

    mma_chunk(sbase + STAGE_, lane, wm, wn, acc);

    epilogue_stats(acc, bias, Y, gsum, gss, m0, wm, wn, lane);
}

__global__ void finalize_stats(const float* __restrict__ gsum, const float* __restrict__ gss,
                               const float* __restrict__ g, const float* __restrict__ be,
                               float* __restrict__ a, float* __restrict__ d) {
    int c = threadIdx.x;
    float mu  = gsum[c] * INV_M;
    float var = gss[c] * INV_M - mu * mu;
    float s = g[c] * rsqrtf(var + BN_EPS_);
    a[c] = s;
    d[c] = be[c] - mu * s;
}

__global__ void bn_out_kernel(float* __restrict__ out,
                              const float* __restrict__ a, const float* __restrict__ d) {
    int i = blockIdx.x * blockDim.x + threadIdx.x;
    int c = (i * 4) & 127;
    float4 v = reinterpret_cast<float4*>(out)[i];
    v.x = fmaxf(a[c + 0] * v.x + d[c + 0], 0.f);
    v.y = fmaxf(a[c + 1] * v.y + d[c + 1], 0.f);
    v.z = fmaxf(a[c + 2] * v.z + d[c + 2], 0.f);
    v.w = fmaxf(a[c + 3] * v.w + d[c + 3], 0.f);
    reinterpret_cast<float4*>(out)[i] = v;
}

extern "C" void kernel_launch(void* const* d_in, const int* in_sizes, int n_in,
                              void* d_out, int out_size) {
    const float* xyz1  = (const float*)d_in[0];
    const float* xyz2  = (const float*)d_in[1];
    const float* feat1 = (const float*)d_in[2];
    const float* feat2 = (const float*)d_in[3];
    const float* w0    = (const float*)d_in[4];
    const float* b0    = (const float*)d_in[5];
    const float* gg0   = (const float*)d_in[6];
    const float* be0   = (const float*)d_in[7];
    const float* w1    = (const float*)d_in[8];
    const float* b1    = (const float*)d_in[9];
    const float* gg1   = (const float*)d_in[10];
    const float* be1   = (const float*)d_in[11];
    float* out = (float*)d_out;

    float *p_y1, *p_sum0, *p_ss0, *p_sum1, *p_ss1, *p_a0, *p_d0, *p_a1, *p_d1;
    __nv_bfloat16 *p_w0h, *p_w0l, *p_w1h, *p_w1l;
    cudaGetSymbolAddress((void**)&p_y1,   g_y1);
    cudaGetSymbolAddress((void**)&p_w0h,  g_wt0h);
    cudaGetSymbolAddress((void**)&p_w0l,  g_wt0l);
    cudaGetSymbolAddress((void**)&p_w1h,  g_wt1h);
    cudaGetSymbolAddress((void**)&p_w1l,  g_wt1l);
    cudaGetSymbolAddress((void**)&p_sum0, g_sum0);
    cudaGetSymbolAddress((void**)&p_ss0,  g_ss0);
    cudaGetSymbolAddress((void**)&p_sum1, g_sum1);
    cudaGetSymbolAddress((void**)&p_ss1,  g_ss1);
    cudaGetSymbolAddress((void**)&p_a0,   g_a0);
    cudaGetSymbolAddress((void**)&p_d0,   g_d0);
    cudaGetSymbolAddress((void**)&p_a1,   g_a1);
    cudaGetSymbolAddress((void**)&p_d1,   g_d1);

    const int smem1 = 2 * STAGE_ + 3072;  // 150528 bytes
    const int smem2 = 2 * STAGE_;         // 147456 bytes
    cudaFuncSetAttribute(gemm1_fused, cudaFuncAttributeMaxDynamicSharedMemorySize, smem1);
    cudaFuncSetAttribute(gemm2_mma,   cudaFuncAttributeMaxDynamicSharedMemorySize, smem2);

    zero_stats_kernel<<<1, 128>>>();
    knn_kernel<<<NPIX / 256, 256>>>(xyz1, xyz2);
    prepw_kernel<<<(192 * 128 + 255) / 256, 256>>>(w0, p_w0h, p_w0l, 192);
    prepw_kernel<<<(128 * 128 + 255) / 256, 256>>>(w1, p_w1h, p_w1l, 128);

    gemm1_fused<<<NPIX / 128, 256, smem1>>>(
        feat1, feat2, p_w0h, p_w0l, b0, p_y1, p_sum0, p_ss0);
    finalize_stats<<<1, 128>>>(p_sum0, p_ss0, gg0, be0, p_a0, p_d0);

    gemm2_mma<<<NPIX / 128, 256, smem2>>>(
        p_y1, p_w1h, p_w1l, b1, p_a0, p_d0, out, p_sum1, p_ss1);
    finalize_stats<<<1, 128>>>(p_sum1, p_ss1, gg1, be1, p_a1, p_d1);

    bn_out_kernel<<<(NPIX * 128 / 4) / 256, 256>>>(out, p_a1, p_d1);
}

// round 13
// speedup vs baseline: 1.6335x; 1.0577x over previous
#include <cuda_runtime.h>
#include <cuda_fp16.h>
#include <cstdint>

#define NPIX   131072          // B*H*W
#define NBATCH 65536           // H*W
#define HH_    64
#define WW_    1024
#define C1_    64
#define C2_    128
#define INV_M  (1.0f/131072.0f)
#define BN_EPS_ 1e-5f

// padded smem tile stride: 64 data + 8 pad elements -> 144B rows
#define LDS_    72
#define A_TILE  18432          // 128 * 72 * 2 bytes
#define STAGE_  55296          // 3 tiles (Ah, Bh, Bl)

__device__ __forceinline__ uint32_t smem_u32(const void* p) {
    uint32_t a;
    asm("{ .reg .u64 t; cvta.to.shared.u64 t, %1; cvt.u32.u64 %0, t; }" : "=r"(a) : "l"(p));
    return a;
}
__device__ __forceinline__ void cp16(uint32_t dst, const void* src) {
    asm volatile("cp.async.ca.shared.global [%0], [%1], 16;" :: "r"(dst), "l"(src));
}
#define CP_COMMIT() asm volatile("cp.async.commit_group;" ::: "memory")
#define CP_WAIT0()  asm volatile("cp.async.wait_group 0;" ::: "memory")

__device__ __forceinline__ void ldm_x4(uint32_t* r, uint32_t addr) {
    asm volatile("ldmatrix.sync.aligned.m8n8.x4.shared.b16 {%0,%1,%2,%3}, [%4];"
        : "=r"(r[0]), "=r"(r[1]), "=r"(r[2]), "=r"(r[3]) : "r"(addr));
}
__device__ __forceinline__ void ldm_x2(uint32_t* r, uint32_t addr) {
    asm volatile("ldmatrix.sync.aligned.m8n8.x2.shared.b16 {%0,%1}, [%2];"
        : "=r"(r[0]), "=r"(r[1]) : "r"(addr));
}
__device__ __forceinline__ void mma_fp16(float* c, const uint32_t* a, const uint32_t* b) {
    asm volatile("mma.sync.aligned.m16n8k16.row.col.f32.f16.f16.f32 "
        "{%0,%1,%2,%3}, {%4,%5,%6,%7}, {%8,%9}, {%0,%1,%2,%3};"
        : "+f"(c[0]), "+f"(c[1]), "+f"(c[2]), "+f"(c[3])
        : "r"(a[0]), "r"(a[1]), "r"(a[2]), "r"(a[3]), "r"(b[0]), "r"(b[1]));
}

// -------- scratch (device globals; no allocs) --------
__device__ float g_y1[(size_t)NPIX * 128];
__device__ __half g_wt0h[3 * 128 * 64], g_wt0l[3 * 128 * 64];
__device__ __half g_wt1h[2 * 128 * 64], g_wt1l[2 * 128 * 64];
__device__ float g_sum0[128], g_ss0[128], g_sum1[128], g_ss1[128];
__device__ float g_a0[128], g_d0[128], g_a1[128], g_d1[128];
__device__ int   g_sel[NPIX * 3];
__device__ float g_coef[NPIX * 3];

// -------- grid KNN: first-3-valid in 5x5 window, inverse-distance coefs --------
__global__ void knn_kernel(const float* __restrict__ xyz1,
                           const float* __restrict__ xyz2) {
    int idx = blockIdx.x * blockDim.x + threadIdx.x;
    int b = idx >> 16;
    int n = idx & (NBATCH - 1);
    int h = n >> 10;
    int w = n & (WW_ - 1);

    const float* q = xyz1 + (size_t)idx * 3;
    float qx = q[0], qy = q[1], qz = q[2];

    int   sel[3] = {0, 0, 0};
    float mk[3]  = {0.f, 0.f, 0.f};
    int cnt = 0;

    #pragma unroll
    for (int dh = -2; dh <= 2; dh++) {
        int hh = h + dh;
        if (hh < 0 || hh >= HH_) continue;
        #pragma unroll
        for (int dw = -2; dw <= 2; dw++) {
            int ww = w + dw;
            if (ww < 0 || ww >= WW_) continue;
            int nn = (hh << 10) + ww;
            const float* p = xyz2 + ((size_t)b * NBATCH + nn) * 3;
            float dx = p[0] - qx, dy = p[1] - qy, dz = p[2] - qz;
            float d2 = dx * dx + dy * dy + dz * dz;
            if (d2 < 10000.0f && cnt < 3) { sel[cnt] = nn; mk[cnt] = 1.f; cnt++; }
        }
    }
    float inv[3]; float dsum = 0.f;
    #pragma unroll
    for (int s = 0; s < 3; s++) {
        const float* p = xyz2 + ((size_t)b * NBATCH + sel[s]) * 3;
        float gx = p[0] * mk[s], gy = p[1] * mk[s], gz = p[2] * mk[s];
        float dx = gx - qx, dy = gy - qy, dz = gz - qz;
        float d2 = dx * dx + dy * dy + dz * dz;
        if (d2 < 1e-10f) d2 = 1e-10f;
        inv[s] = 1.0f / d2;
        dsum += inv[s];
    }
    float rnorm = 1.0f / dsum;
    #pragma unroll
    for (int s = 0; s < 3; s++) {
        g_sel[idx * 3 + s]  = b * NBATCH + sel[s];
        g_coef[idx * 3 + s] = inv[s] * rnorm * mk[s];
    }
}

// -------- prep: both weight transposes (fp16 hi/lo) + zero stat accumulators --------
__global__ void prep_kernel(const float* __restrict__ w0, const float* __restrict__ w1) {
    int t = blockIdx.x * 256 + threadIdx.x;
    if (t < 128) {
        g_sum0[t] = 0.f; g_ss0[t] = 0.f;
        g_sum1[t] = 0.f; g_ss1[t] = 0.f;
    }
    if (t < 192 * 128) {
        int k = t >> 7, n = t & 127;
        float v = w0[t];
        __half h = __float2half(v);
        __half l = __float2half(v - __half2float(h));
        int o = ((k >> 6) * 128 + n) * 64 + (k & 63);
        g_wt0h[o] = h; g_wt0l[o] = l;
    } else {
        int t2 = t - 192 * 128;
        if (t2 < 128 * 128) {
            int k = t2 >> 7, n = t2 & 127;
            float v = w1[t2];
            __half h = __float2half(v);
            __half l = __float2half(v - __half2float(h));
            int o = ((k >> 6) * 128 + n) * 64 + (k & 63);
            g_wt1h[o] = h; g_wt1l[o] = l;
        }
    }
}

// -------- shared MMA-on-chunk + epilogue helpers --------
// stage layout: [Ah | Bh | Bl], each 18432 B
__device__ __forceinline__ void mma_chunk(uint32_t sb, int lane, int wm, int wn,
                                          float (&acc)[2][8][4]) {
    #pragma unroll
    for (int ks = 0; ks < 4; ks++) {
        uint32_t ah[2][4];
        #pragma unroll
        for (int mi = 0; mi < 2; mi++) {
            int row = wm + mi * 16 + (lane & 15);
            int col = ks * 16 + (lane >> 4) * 8;
            ldm_x4(ah[mi], sb + (uint32_t)(row * LDS_ + col) * 2);
        }
        #pragma unroll
        for (int ni = 0; ni < 8; ni++) {
            int row = wn + ni * 8 + (lane & 7);
            int col = ks * 16 + ((lane >> 3) & 1) * 8;
            uint32_t off = (uint32_t)(row * LDS_ + col) * 2;
            uint32_t bh[2], bl[2];
            ldm_x2(bh, sb + A_TILE + off);
            ldm_x2(bl, sb + 2 * A_TILE + off);
            #pragma unroll
            for (int mi = 0; mi < 2; mi++) {
                mma_fp16(acc[mi][ni], ah[mi], bh);
                mma_fp16(acc[mi][ni], ah[mi], bl);
            }
        }
    }
}

// epilogue: bias add + store + per-channel sum/sumsq (shfl-reduce + global red)
__device__ __forceinline__ void epilogue_stats(float (&acc)[2][8][4],
        const float* __restrict__ bias, float* __restrict__ Y,
        float* __restrict__ gsum, float* __restrict__ gss,
        int m0, int wm, int wn, int lane) {
    float2 bb[8];
    #pragma unroll
    for (int ni = 0; ni < 8; ni++) {
        int n = wn + ni * 8 + (lane & 3) * 2;
        bb[ni].x = __ldg(bias + n);
        bb[ni].y = __ldg(bias + n + 1);
    }
    float s[16], q[16];
    #pragma unroll
    for (int t = 0; t < 16; t++) { s[t] = 0.f; q[t] = 0.f; }

    #pragma unroll
    for (int mi = 0; mi < 2; mi++) {
        int r0 = m0 + wm + mi * 16 + (lane >> 2);
        #pragma unroll
        for (int ni = 0; ni < 8; ni++) {
            int n = wn + ni * 8 + (lane & 3) * 2;
            float v0 = acc[mi][ni][0] + bb[ni].x;
            float v1 = acc[mi][ni][1] + bb[ni].y;
            float v2 = acc[mi][ni][2] + bb[ni].x;
            float v3 = acc[mi][ni][3] + bb[ni].y;
            *reinterpret_cast<float2*>(Y + (size_t)r0 * 128 + n) = make_float2(v0, v1);
            *reinterpret_cast<float2*>(Y + (size_t)(r0 + 8) * 128 + n) = make_float2(v2, v3);
            s[ni * 2 + 0] += v0 + v2;          s[ni * 2 + 1] += v1 + v3;
            q[ni * 2 + 0] += v0 * v0 + v2 * v2; q[ni * 2 + 1] += v1 * v1 + v3 * v3;
        }
    }
    #pragma unroll
    for (int t = 0; t < 16; t++) {
        #pragma unroll
        for (int o = 4; o < 32; o <<= 1) {
            s[t] += __shfl_xor_sync(0xffffffffu, s[t], o);
            q[t] += __shfl_xor_sync(0xffffffffu, q[t], o);
        }
    }
    if (lane < 4) {
        #pragma unroll
        for (int ni = 0; ni < 8; ni++) {
            int col = wn + ni * 8 + lane * 2;
            atomicAdd(gsum + col,     s[ni * 2 + 0]);
            atomicAdd(gsum + col + 1, s[ni * 2 + 1]);
            atomicAdd(gss  + col,     q[ni * 2 + 0]);
            atomicAdd(gss  + col + 1, q[ni * 2 + 1]);
        }
    }
}

// fp32 float4 -> fp16 hi, store to stage A region
__device__ __forceinline__ void storeAh(const float4& v, char* smg, int stg,
                                        int row, int seg) {
    __half2 h01 = __floats2half2_rn(v.x, v.y);
    __half2 h23 = __floats2half2_rn(v.z, v.w);
    uint2 hv;
    hv.x = *reinterpret_cast<const uint32_t*>(&h01);
    hv.y = *reinterpret_cast<const uint32_t*>(&h23);
    *reinterpret_cast<uint2*>(smg + stg * STAGE_ + (uint32_t)(row * LDS_ + seg * 4) * 2) = hv;
}

// -------- GEMM1 with fused gather/interp/concat A-build + fused stats --------
__global__ __launch_bounds__(256)
void gemm1_fused(const float* __restrict__ feat1,
                 const float* __restrict__ feat2,
                 const __half* __restrict__ Bh,
                 const __half* __restrict__ Bl,
                 const float* __restrict__ bias,
                 float* __restrict__ Y,
                 float* __restrict__ gsum, float* __restrict__ gss) {
    extern __shared__ __align__(16) char smg[];
    const uint32_t sbase = smem_u32(smg);
    int*   ssel  = reinterpret_cast<int*>(smg + 2 * STAGE_);
    float* scoef = reinterpret_cast<float*>(smg + 2 * STAGE_ + 1536);
    const int tid = threadIdx.x, lane = tid & 31, wid = tid >> 5;
    const int m0 = blockIdx.x * 128;
    const int wm = (wid & 3) * 32, wn = (wid >> 2) * 64;

    float acc[2][8][4];
    #pragma unroll
    for (int mi = 0; mi < 2; mi++)
        #pragma unroll
        for (int ni = 0; ni < 8; ni++)
            #pragma unroll
            for (int j = 0; j < 4; j++) acc[mi][ni][j] = 0.f;

    auto loadB = [&](int c, int stg) {
        uint32_t sb = sbase + stg * STAGE_;
        #pragma unroll
        for (int i = 0; i < 4; i++) {
            int u = i * 256 + tid, row = u >> 3, seg = u & 7;
            uint32_t so = (uint32_t)(row * LDS_ + seg * 8) * 2;
            int gb = c * 8192 + row * 64 + seg * 8;
            cp16(sb + A_TILE + so, Bh + gb);
            cp16(sb + 2 * A_TILE + so, Bl + gb);
        }
        CP_COMMIT();
    };
    auto gather = [&](int row, int seg, int half) -> float4 {
        int   s0 = ssel[row * 3 + 0], s1 = ssel[row * 3 + 1], s2 = ssel[row * 3 + 2];
        float c0 = scoef[row * 3 + 0], c1 = scoef[row * 3 + 1], c2 = scoef[row * 3 + 2];
        int off = half * 64 + seg * 4;
        float4 a = *reinterpret_cast<const float4*>(feat2 + (size_t)s0 * 128 + off);
        float4 b = *reinterpret_cast<const float4*>(feat2 + (size_t)s1 * 128 + off);
        float4 c = *reinterpret_cast<const float4*>(feat2 + (size_t)s2 * 128 + off);
        float4 r;
        r.x = c0 * a.x + c1 * b.x + c2 * c.x;
        r.y = c0 * a.y + c1 * b.y + c2 * c.y;
        r.z = c0 * a.z + c1 * b.z + c2 * c.z;
        r.w = c0 * a.w + c1 * b.w + c2 * c.w;
        return r;
    };

    // stage sel/coef for the block's 128 pixels
    for (int t = tid; t < 384; t += 256) {
        ssel[t]  = g_sel[(size_t)m0 * 3 + t];
        scoef[t] = g_coef[(size_t)m0 * 3 + t];
    }

    // chunk 0 A = feat1 (direct)
    #pragma unroll
    for (int i = 0; i < 8; i++) {
        int u = i * 256 + tid, row = u >> 4, seg = u & 15;
        float4 v = *reinterpret_cast<const float4*>(
            feat1 + (size_t)(m0 + row) * 64 + seg * 4);
        storeAh(v, smg, 0, row, seg);
    }
    loadB(0, 0);
    __syncthreads();   // sel/coef visible; A s0 stored

    // prefetch chunk-1 interp (feat2 ch 0-63)
    float4 pre[8];
    #pragma unroll
    for (int i = 0; i < 8; i++) {
        int u = i * 256 + tid, row = u >> 4, seg = u & 15;
        pre[i] = gather(row, seg, 0);
    }
    loadB(1, 1);
    CP_WAIT0(); __syncthreads();

    mma_chunk(sbase, lane, wm, wn, acc);              // chunk 0

    #pragma unroll
    for (int i = 0; i < 8; i++) {
        int u = i * 256 + tid, row = u >> 4, seg = u & 15;
        storeAh(pre[i], smg, 1, row, seg);
        pre[i] = gather(row, seg, 1);                 // prefetch chunk-2 interp
    }
    __syncthreads();                                  // all past mma(s0); A s1 ready
    loadB(2, 0);                                      // overwrite s0 B

    mma_chunk(sbase + STAGE_, lane, wm, wn, acc);     // chunk 1

    CP_WAIT0();
    #pragma unroll
    for (int i = 0; i < 8; i++) {
        int u = i * 256 + tid, row = u >> 4, seg = u & 15;
        storeAh(pre[i], smg, 0, row, seg);
    }
    __syncthreads();

    mma_chunk(sbase, lane, wm, wn, acc);              // chunk 2

    epilogue_stats(acc, bias, Y, gsum, gss, m0, wm, wn, lane);
}

// -------- GEMM2: fp32 A with fused BN+ReLU, pipelined, fused stats --------
__global__ __launch_bounds__(256)
void gemm2_mma(const float* __restrict__ Af,
               const __half* __restrict__ Bh,
               const __half* __restrict__ Bl,
               const float* __restrict__ bias,
               const float* __restrict__ bna, const float* __restrict__ bnd,
               float* __restrict__ Y,
               float* __restrict__ gsum, float* __restrict__ gss) {
    extern __shared__ __align__(16) char smg[];
    const uint32_t sbase = smem_u32(smg);
    const int tid = threadIdx.x, lane = tid & 31, wid = tid >> 5;
    const int m0 = blockIdx.x * 128;
    const int wm = (wid & 3) * 32, wn = (wid >> 2) * 64;

    float acc[2][8][4];
    #pragma unroll
    for (int mi = 0; mi < 2; mi++)
        #pragma unroll
        for (int ni = 0; ni < 8; ni++)
            #pragma unroll
            for (int j = 0; j < 4; j++) acc[mi][ni][j] = 0.f;

    auto bnrelu = [&](float4 v, int c, int seg) -> float4 {
        int k = c * 64 + seg * 4;
        v.x = fmaxf(__ldg(bna + k + 0) * v.x + __ldg(bnd + k + 0), 0.f);
        v.y = fmaxf(__ldg(bna + k + 1) * v.y + __ldg(bnd + k + 1), 0.f);
        v.z = fmaxf(__ldg(bna + k + 2) * v.z + __ldg(bnd + k + 2), 0.f);
        v.w = fmaxf(__ldg(bna + k + 3) * v.w + __ldg(bnd + k + 3), 0.f);
        return v;
    };
    auto loadB = [&](int c, int stg) {
        uint32_t sb = sbase + stg * STAGE_;
        #pragma unroll
        for (int i = 0; i < 4; i++) {
            int u = i * 256 + tid, row = u >> 3, seg = u & 7;
            uint32_t so = (uint32_t)(row * LDS_ + seg * 8) * 2;
            int gb = c * 8192 + row * 64 + seg * 8;
            cp16(sb + A_TILE + so, Bh + gb);
            cp16(sb + 2 * A_TILE + so, Bl + gb);
        }
        CP_COMMIT();
    };

    #pragma unroll
    for (int i = 0; i < 8; i++) {
        int u = i * 256 + tid, row = u >> 4, seg = u & 15;
        float4 v = *reinterpret_cast<const float4*>(Af + (size_t)(m0 + row) * 128 + seg * 4);
        storeAh(bnrelu(v, 0, seg), smg, 0, row, seg);
    }
    loadB(0, 0);
    float4 pre[8];
    #pragma unroll
    for (int i = 0; i < 8; i++) {
        int u = i * 256 + tid, row = u >> 4, seg = u & 15;
        pre[i] = *reinterpret_cast<const float4*>(Af + (size_t)(m0 + row) * 128 + 64 + seg * 4);
    }
    loadB(1, 1);
    CP_WAIT0(); __syncthreads();

    mma_chunk(sbase, lane, wm, wn, acc);

    #pragma unroll
    for (int i = 0; i < 8; i++) {
        int u = i * 256 + tid, row = u >> 4, seg = u & 15;
        storeAh(bnrelu(pre[i], 1, seg), smg, 1, row, seg);
    }
    __syncthreads();

    mma_chunk(sbase + STAGE_, lane, wm, wn, acc);

    epilogue_stats(acc, bias, Y, gsum, gss, m0, wm, wn, lane);
}

__global__ void finalize_stats(const float* __restrict__ gsum, const float* __restrict__ gss,
                               const float* __restrict__ g, const float* __restrict__ be,
                               float* __restrict__ a, float* __restrict__ d) {
    int c = threadIdx.x;
    float mu  = gsum[c] * INV_M;
    float var = gss[c] * INV_M - mu * mu;
    float s = g[c] * rsqrtf(var + BN_EPS_);
    a[c] = s;
    d[c] = be[c] - mu * s;
}

__global__ void bn_out_kernel(float* __restrict__ out,
                              const float* __restrict__ a, const float* __restrict__ d) {
    int i = blockIdx.x * blockDim.x + threadIdx.x;
    int c = (i * 4) & 127;
    float4 v = reinterpret_cast<float4*>(out)[i];
    v.x = fmaxf(a[c + 0] * v.x + d[c + 0], 0.f);
    v.y = fmaxf(a[c + 1] * v.y + d[c + 1], 0.f);
    v.z = fmaxf(a[c + 2] * v.z + d[c + 2], 0.f);
    v.w = fmaxf(a[c + 3] * v.w + d[c + 3], 0.f);
    reinterpret_cast<float4*>(out)[i] = v;
}

extern "C" void kernel_launch(void* const* d_in, const int* in_sizes, int n_in,
                              void* d_out, int out_size) {
    const float* xyz1  = (const float*)d_in[0];
    const float* xyz2  = (const float*)d_in[1];
    const float* feat1 = (const float*)d_in[2];
    const float* feat2 = (const float*)d_in[3];
    const float* w0    = (const float*)d_in[4];
    const float* b0    = (const float*)d_in[5];
    const float* gg0   = (const float*)d_in[6];
    const float* be0   = (const float*)d_in[7];
    const float* w1    = (const float*)d_in[8];
    const float* b1    = (const float*)d_in[9];
    const float* gg1   = (const float*)d_in[10];
    const float* be1   = (const float*)d_in[11];
    float* out = (float*)d_out;

    float *p_y1, *p_sum0, *p_ss0, *p_sum1, *p_ss1, *p_a0, *p_d0, *p_a1, *p_d1;
    __half *p_w0h, *p_w0l, *p_w1h, *p_w1l;
    cudaGetSymbolAddress((void**)&p_y1,   g_y1);
    cudaGetSymbolAddress((void**)&p_w0h,  g_wt0h);
    cudaGetSymbolAddress((void**)&p_w0l,  g_wt0l);
    cudaGetSymbolAddress((void**)&p_w1h,  g_wt1h);
    cudaGetSymbolAddress((void**)&p_w1l,  g_wt1l);
    cudaGetSymbolAddress((void**)&p_sum0, g_sum0);
    cudaGetSymbolAddress((void**)&p_ss0,  g_ss0);
    cudaGetSymbolAddress((void**)&p_sum1, g_sum1);
    cudaGetSymbolAddress((void**)&p_ss1,  g_ss1);
    cudaGetSymbolAddress((void**)&p_a0,   g_a0);
    cudaGetSymbolAddress((void**)&p_d0,   g_d0);
    cudaGetSymbolAddress((void**)&p_a1,   g_a1);
    cudaGetSymbolAddress((void**)&p_d1,   g_d1);

    const int smem1 = 2 * STAGE_ + 3072;  // 113664 bytes
    const int smem2 = 2 * STAGE_;         // 110592 bytes
    cudaFuncSetAttribute(gemm1_fused, cudaFuncAttributeMaxDynamicSharedMemorySize, smem1);
    cudaFuncSetAttribute(gemm2_mma,   cudaFuncAttributeMaxDynamicSharedMemorySize, smem2);

    knn_kernel<<<NPIX / 256, 256>>>(xyz1, xyz2);
    prep_kernel<<<(192 * 128 + 128 * 128 + 255) / 256, 256>>>(w0, w1);

    gemm1_fused<<<NPIX / 128, 256, smem1>>>(
        feat1, feat2, p_w0h, p_w0l, b0, p_y1, p_sum0, p_ss0);
    finalize_stats<<<1, 128>>>(p_sum0, p_ss0, gg0, be0, p_a0, p_d0);

    gemm2_mma<<<NPIX / 128, 256, smem2>>>(
        p_y1, p_w1h, p_w1l, b1, p_a0, p_d0, out, p_sum1, p_ss1);
    finalize_stats<<<1, 128>>>(p_sum1, p_ss1, gg1, be1, p_a1, p_d1);

    bn_out_kernel<<<(NPIX * 128 / 4) / 256, 256>>>(out, p_a1, p_d1);
}

// round 15
// speedup vs baseline: 1.7129x; 1.0486x over previous
#include <cuda_runtime.h>
#include <cuda_fp16.h>
#include <cstdint>

#define NPIX   131072          // B*H*W
#define NBATCH 65536           // H*W
#define HH_    64
#define WW_    1024
#define INV_M  (1.0f/131072.0f)
#define BN_EPS_ 1e-5f

// padded smem tile stride: 64 data + 8 pad elements -> 144B rows
#define LDS_    72
#define A_TILE  18432          // 128 * 72 * 2 bytes
#define STAGE_  55296          // 3 tiles (Ah, Bh, Bl)

__device__ __forceinline__ uint32_t smem_u32(const void* p) {
    uint32_t a;
    asm("{ .reg .u64 t; cvta.to.shared.u64 t, %1; cvt.u32.u64 %0, t; }" : "=r"(a) : "l"(p));
    return a;
}
__device__ __forceinline__ void cp16(uint32_t dst, const void* src) {
    asm volatile("cp.async.ca.shared.global [%0], [%1], 16;" :: "r"(dst), "l"(src));
}
#define CP_COMMIT() asm volatile("cp.async.commit_group;" ::: "memory")
#define CP_WAIT0()  asm volatile("cp.async.wait_group 0;" ::: "memory")

__device__ __forceinline__ void ldm_x4(uint32_t* r, uint32_t addr) {
    asm volatile("ldmatrix.sync.aligned.m8n8.x4.shared.b16 {%0,%1,%2,%3}, [%4];"
        : "=r"(r[0]), "=r"(r[1]), "=r"(r[2]), "=r"(r[3]) : "r"(addr));
}
__device__ __forceinline__ void ldm_x2(uint32_t* r, uint32_t addr) {
    asm volatile("ldmatrix.sync.aligned.m8n8.x2.shared.b16 {%0,%1}, [%2];"
        : "=r"(r[0]), "=r"(r[1]) : "r"(addr));
}
__device__ __forceinline__ void mma_fp16(float* c, const uint32_t* a, const uint32_t* b) {
    asm volatile("mma.sync.aligned.m16n8k16.row.col.f32.f16.f16.f32 "
        "{%0,%1,%2,%3}, {%4,%5,%6,%7}, {%8,%9}, {%0,%1,%2,%3};"
        : "+f"(c[0]), "+f"(c[1]), "+f"(c[2]), "+f"(c[3])
        : "r"(a[0]), "r"(a[1]), "r"(a[2]), "r"(a[3]), "r"(b[0]), "r"(b[1]));
}

// -------- scratch (device globals; no allocs) --------
__device__ __half g_y1h[(size_t)NPIX * 128];
__device__ __half g_wt0h[3 * 128 * 64], g_wt0l[3 * 128 * 64];
__device__ __half g_wt1h[2 * 128 * 64], g_wt1l[2 * 128 * 64];
__device__ float g_sum0[128], g_ss0[128], g_sum1[128], g_ss1[128];
__device__ int   g_sel[NPIX * 3];
__device__ float g_coef[NPIX * 3];

// -------- grid KNN: first-3-valid in 5x5 window, inverse-distance coefs --------
__global__ void knn_kernel(const float* __restrict__ xyz1,
                           const float* __restrict__ xyz2) {
    int idx = blockIdx.x * blockDim.x + threadIdx.x;
    int b = idx >> 16;
    int n = idx & (NBATCH - 1);
    int h = n >> 10;
    int w = n & (WW_ - 1);

    const float* q = xyz1 + (size_t)idx * 3;
    float qx = q[0], qy = q[1], qz = q[2];

    int   sel[3] = {0, 0, 0};
    float mk[3]  = {0.f, 0.f, 0.f};
    int cnt = 0;

    #pragma unroll
    for (int dh = -2; dh <= 2; dh++) {
        int hh = h + dh;
        if (hh < 0 || hh >= HH_) continue;
        #pragma unroll
        for (int dw = -2; dw <= 2; dw++) {
            int ww = w + dw;
            if (ww < 0 || ww >= WW_) continue;
            int nn = (hh << 10) + ww;
            const float* p = xyz2 + ((size_t)b * NBATCH + nn) * 3;
            float dx = p[0] - qx, dy = p[1] - qy, dz = p[2] - qz;
            float d2 = dx * dx + dy * dy + dz * dz;
            if (d2 < 10000.0f && cnt < 3) { sel[cnt] = nn; mk[cnt] = 1.f; cnt++; }
        }
    }
    float inv[3]; float dsum = 0.f;
    #pragma unroll
    for (int s = 0; s < 3; s++) {
        const float* p = xyz2 + ((size_t)b * NBATCH + sel[s]) * 3;
        float gx = p[0] * mk[s], gy = p[1] * mk[s], gz = p[2] * mk[s];
        float dx = gx - qx, dy = gy - qy, dz = gz - qz;
        float d2 = dx * dx + dy * dy + dz * dz;
        if (d2 < 1e-10f) d2 = 1e-10f;
        inv[s] = 1.0f / d2;
        dsum += inv[s];
    }
    float rnorm = 1.0f / dsum;
    #pragma unroll
    for (int s = 0; s < 3; s++) {
        g_sel[idx * 3 + s]  = b * NBATCH + sel[s];
        g_coef[idx * 3 + s] = inv[s] * rnorm * mk[s];
    }
}

// -------- prep: both weight transposes (fp16 hi/lo) + zero stat accumulators --------
__global__ void prep_kernel(const float* __restrict__ w0, const float* __restrict__ w1) {
    int t = blockIdx.x * 256 + threadIdx.x;
    if (t < 128) {
        g_sum0[t] = 0.f; g_ss0[t] = 0.f;
        g_sum1[t] = 0.f; g_ss1[t] = 0.f;
    }
    if (t < 192 * 128) {
        int k = t >> 7, n = t & 127;
        float v = w0[t];
        __half h = __float2half(v);
        __half l = __float2half(v - __half2float(h));
        int o = ((k >> 6) * 128 + n) * 64 + (k & 63);
        g_wt0h[o] = h; g_wt0l[o] = l;
    } else {
        int t2 = t - 192 * 128;
        if (t2 < 128 * 128) {
            int k = t2 >> 7, n = t2 & 127;
            float v = w1[t2];
            __half h = __float2half(v);
            __half l = __float2half(v - __half2float(h));
            int o = ((k >> 6) * 128 + n) * 64 + (k & 63);
            g_wt1h[o] = h; g_wt1l[o] = l;
        }
    }
}

// -------- shared MMA-on-chunk helper: stage = [Ah | Bh | Bl] --------
__device__ __forceinline__ void mma_chunk(uint32_t sb, int lane, int wm, int wn,
                                          float (&acc)[2][8][4]) {
    #pragma unroll
    for (int ks = 0; ks < 4; ks++) {
        uint32_t ah[2][4];
        #pragma unroll
        for (int mi = 0; mi < 2; mi++) {
            int row = wm + mi * 16 + (lane & 15);
            int col = ks * 16 + (lane >> 4) * 8;
            ldm_x4(ah[mi], sb + (uint32_t)(row * LDS_ + col) * 2);
        }
        #pragma unroll
        for (int ni = 0; ni < 8; ni++) {
            int row = wn + ni * 8 + (lane & 7);
            int col = ks * 16 + ((lane >> 3) & 1) * 8;
            uint32_t off = (uint32_t)(row * LDS_ + col) * 2;
            uint32_t bh[2], bl[2];
            ldm_x2(bh, sb + A_TILE + off);
            ldm_x2(bl, sb + 2 * A_TILE + off);
            #pragma unroll
            for (int mi = 0; mi < 2; mi++) {
                mma_fp16(acc[mi][ni], ah[mi], bh);
                mma_fp16(acc[mi][ni], ah[mi], bl);
            }
        }
    }
}

// stats reduce + global atomics (shared by both epilogues)
__device__ __forceinline__ void stats_reduce(float (&s)[16], float (&q)[16],
        float* __restrict__ gsum, float* __restrict__ gss, int wn, int lane) {
    #pragma unroll
    for (int t = 0; t < 16; t++) {
        #pragma unroll
        for (int o = 4; o < 32; o <<= 1) {
            s[t] += __shfl_xor_sync(0xffffffffu, s[t], o);
            q[t] += __shfl_xor_sync(0xffffffffu, q[t], o);
        }
    }
    if (lane < 4) {
        #pragma unroll
        for (int ni = 0; ni < 8; ni++) {
            int col = wn + ni * 8 + lane * 2;
            atomicAdd(gsum + col,     s[ni * 2 + 0]);
            atomicAdd(gsum + col + 1, s[ni * 2 + 1]);
            atomicAdd(gss  + col,     q[ni * 2 + 0]);
            atomicAdd(gss  + col + 1, q[ni * 2 + 1]);
        }
    }
}

// fp32 float4 -> fp16, store 4 halves to stage A region
__device__ __forceinline__ void storeAh(const float4& v, char* smg, int stg,
                                        int row, int seg) {
    __half2 h01 = __floats2half2_rn(v.x, v.y);
    __half2 h23 = __floats2half2_rn(v.z, v.w);
    uint2 hv;
    hv.x = *reinterpret_cast<const uint32_t*>(&h01);
    hv.y = *reinterpret_cast<const uint32_t*>(&h23);
    *reinterpret_cast<uint2*>(smg + stg * STAGE_ + (uint32_t)(row * LDS_ + seg * 4) * 2) = hv;
}

// -------- GEMM1: fused gather/interp/concat A-build, fp16 y1 out, fused stats --------
__global__ __launch_bounds__(256, 2)
void gemm1_fused(const float* __restrict__ feat1,
                 const float* __restrict__ feat2,
                 const __half* __restrict__ Bh,
                 const __half* __restrict__ Bl,
                 const float* __restrict__ bias,
                 __half* __restrict__ Y,
                 float* __restrict__ gsum, float* __restrict__ gss) {
    extern __shared__ __align__(16) char smg[];
    const uint32_t sbase = smem_u32(smg);
    int*   ssel  = reinterpret_cast<int*>(smg + 2 * STAGE_);
    float* scoef = reinterpret_cast<float*>(smg + 2 * STAGE_ + 1536);
    const int tid = threadIdx.x, lane = tid & 31, wid = tid >> 5;
    const int m0 = blockIdx.x * 128;
    const int wm = (wid & 3) * 32, wn = (wid >> 2) * 64;

    float acc[2][8][4];
    #pragma unroll
    for (int mi = 0; mi < 2; mi++)
        #pragma unroll
        for (int ni = 0; ni < 8; ni++)
            #pragma unroll
            for (int j = 0; j < 4; j++) acc[mi][ni][j] = 0.f;

    auto loadB = [&](int c, int stg) {
        uint32_t sb = sbase + stg * STAGE_;
        #pragma unroll
        for (int i = 0; i < 4; i++) {
            int u = i * 256 + tid, row = u >> 3, seg = u & 7;
            uint32_t so = (uint32_t)(row * LDS_ + seg * 8) * 2;
            int gb = c * 8192 + row * 64 + seg * 8;
            cp16(sb + A_TILE + so, Bh + gb);
            cp16(sb + 2 * A_TILE + so, Bl + gb);
        }
        CP_COMMIT();
    };
    auto gatherA = [&](int stg, int half) {
        #pragma unroll
        for (int i = 0; i < 8; i++) {
            int u = i * 256 + tid, row = u >> 4, seg = u & 15;
            int   s0 = ssel[row * 3 + 0], s1 = ssel[row * 3 + 1], s2 = ssel[row * 3 + 2];
            float c0 = scoef[row * 3 + 0], c1 = scoef[row * 3 + 1], c2 = scoef[row * 3 + 2];
            int off = half * 64 + seg * 4;
            float4 a = *reinterpret_cast<const float4*>(feat2 + (size_t)s0 * 128 + off);
            float4 b = *reinterpret_cast<const float4*>(feat2 + (size_t)s1 * 128 + off);
            float4 c = *reinterpret_cast<const float4*>(feat2 + (size_t)s2 * 128 + off);
            float4 r;
            r.x = c0 * a.x + c1 * b.x + c2 * c.x;
            r.y = c0 * a.y + c1 * b.y + c2 * c.y;
            r.z = c0 * a.z + c1 * b.z + c2 * c.z;
            r.w = c0 * a.w + c1 * b.w + c2 * c.w;
            storeAh(r, smg, stg, row, seg);
        }
    };

    // stage sel/coef for the block's 128 pixels
    for (int t = tid; t < 384; t += 256) {
        ssel[t]  = g_sel[(size_t)m0 * 3 + t];
        scoef[t] = g_coef[(size_t)m0 * 3 + t];
    }
    // chunk 0 A = feat1 (direct)
    #pragma unroll
    for (int i = 0; i < 8; i++) {
        int u = i * 256 + tid, row = u >> 4, seg = u & 15;
        float4 v = *reinterpret_cast<const float4*>(
            feat1 + (size_t)(m0 + row) * 64 + seg * 4);
        storeAh(v, smg, 0, row, seg);
    }
    loadB(0, 0);
    loadB(1, 1);
    __syncthreads();            // ssel/scoef visible
    gatherA(1, 0);              // chunk-1 A -> stage 1
    CP_WAIT0(); __syncthreads();

    mma_chunk(sbase, lane, wm, wn, acc);              // chunk 0
    __syncthreads();
    loadB(2, 0);                                      // async B2 -> s0
    gatherA(0, 1);                                    // chunk-2 A -> s0
    mma_chunk(sbase + STAGE_, lane, wm, wn, acc);     // chunk 1 (overlaps B2)
    CP_WAIT0(); __syncthreads();
    mma_chunk(sbase, lane, wm, wn, acc);              // chunk 2

    // epilogue: bias, fp16 store, stats
    float2 bb[8];
    #pragma unroll
    for (int ni = 0; ni < 8; ni++) {
        int n = wn + ni * 8 + (lane & 3) * 2;
        bb[ni].x = __ldg(bias + n);
        bb[ni].y = __ldg(bias + n + 1);
    }
    float s[16], q[16];
    #pragma unroll
    for (int t = 0; t < 16; t++) { s[t] = 0.f; q[t] = 0.f; }
    #pragma unroll
    for (int mi = 0; mi < 2; mi++) {
        int r0 = m0 + wm + mi * 16 + (lane >> 2);
        #pragma unroll
        for (int ni = 0; ni < 8; ni++) {
            int n = wn + ni * 8 + (lane & 3) * 2;
            float v0 = acc[mi][ni][0] + bb[ni].x;
            float v1 = acc[mi][ni][1] + bb[ni].y;
            float v2 = acc[mi][ni][2] + bb[ni].x;
            float v3 = acc[mi][ni][3] + bb[ni].y;
            __half2 p0 = __floats2half2_rn(v0, v1);
            __half2 p1 = __floats2half2_rn(v2, v3);
            *reinterpret_cast<__half2*>(Y + (size_t)r0 * 128 + n) = p0;
            *reinterpret_cast<__half2*>(Y + (size_t)(r0 + 8) * 128 + n) = p1;
            s[ni * 2 + 0] += v0 + v2;          s[ni * 2 + 1] += v1 + v3;
            q[ni * 2 + 0] += v0 * v0 + v2 * v2; q[ni * 2 + 1] += v1 * v1 + v3 * v3;
        }
    }
    stats_reduce(s, q, gsum, gss, wn, lane);
}

// -------- GEMM2: fp16 y1 in, inline BN-coef compute + BN+ReLU, fused stats --------
__global__ __launch_bounds__(256, 2)
void gemm2_mma(const __half* __restrict__ Ah,
               const __half* __restrict__ Bh,
               const __half* __restrict__ Bl,
               const float* __restrict__ bias,
               const float* __restrict__ g0sum, const float* __restrict__ g0ss,
               const float* __restrict__ gg, const float* __restrict__ be,
               float* __restrict__ Y,
               float* __restrict__ gsum, float* __restrict__ gss) {
    extern __shared__ __align__(16) char smg[];
    const uint32_t sbase = smem_u32(smg);
    float* sa = reinterpret_cast<float*>(smg + 2 * STAGE_);
    float* sd = sa + 128;
    const int tid = threadIdx.x, lane = tid & 31, wid = tid >> 5;
    const int m0 = blockIdx.x * 128;
    const int wm = (wid & 3) * 32, wn = (wid >> 2) * 64;

    // inline finalize of layer-0 BN coefs
    if (tid < 128) {
        float mu  = g0sum[tid] * INV_M;
        float var = g0ss[tid] * INV_M - mu * mu;
        float sc = gg[tid] * rsqrtf(var + BN_EPS_);
        sa[tid] = sc;
        sd[tid] = be[tid] - mu * sc;
    }

    float acc[2][8][4];
    #pragma unroll
    for (int mi = 0; mi < 2; mi++)
        #pragma unroll
        for (int ni = 0; ni < 8; ni++)
            #pragma unroll
            for (int j = 0; j < 4; j++) acc[mi][ni][j] = 0.f;

    auto loadB = [&](int c, int stg) {
        uint32_t sb = sbase + stg * STAGE_;
        #pragma unroll
        for (int i = 0; i < 4; i++) {
            int u = i * 256 + tid, row = u >> 3, seg = u & 7;
            uint32_t so = (uint32_t)(row * LDS_ + seg * 8) * 2;
            int gb = c * 8192 + row * 64 + seg * 8;
            cp16(sb + A_TILE + so, Bh + gb);
            cp16(sb + 2 * A_TILE + so, Bl + gb);
        }
        CP_COMMIT();
    };

    loadB(0, 0);
    loadB(1, 1);
    __syncthreads();            // sa/sd visible

    // A chunks: read fp16 y1, BN+ReLU, restore fp16 (8 halves/thread/iter)
    #pragma unroll
    for (int c = 0; c < 2; c++) {
        #pragma unroll
        for (int i = 0; i < 4; i++) {
            int u = i * 256 + tid, row = u >> 3, seg = u & 7;   // 8 segs x 8 halves
            uint4 raw = *reinterpret_cast<const uint4*>(
                Ah + (size_t)(m0 + row) * 128 + c * 64 + seg * 8);
            const __half2* hp = reinterpret_cast<const __half2*>(&raw);
            uint4 outv;
            __half2* op = reinterpret_cast<__half2*>(&outv);
            #pragma unroll
            for (int j = 0; j < 4; j++) {
                float2 f = __half22float2(hp[j]);
                int k = c * 64 + seg * 8 + j * 2;
                f.x = fmaxf(sa[k] * f.x + sd[k], 0.f);
                f.y = fmaxf(sa[k + 1] * f.y + sd[k + 1], 0.f);
                op[j] = __floats2half2_rn(f.x, f.y);
            }
            *reinterpret_cast<uint4*>(smg + c * STAGE_ +
                (uint32_t)(row * LDS_ + seg * 8) * 2) = outv;
        }
    }
    CP_WAIT0(); __syncthreads();

    mma_chunk(sbase, lane, wm, wn, acc);
    mma_chunk(sbase + STAGE_, lane, wm, wn, acc);

    // epilogue: bias, fp32 store, stats
    float2 bb[8];
    #pragma unroll
    for (int ni = 0; ni < 8; ni++) {
        int n = wn + ni * 8 + (lane & 3) * 2;
        bb[ni].x = __ldg(bias + n);
        bb[ni].y = __ldg(bias + n + 1);
    }
    float s[16], q[16];
    #pragma unroll
    for (int t = 0; t < 16; t++) { s[t] = 0.f; q[t] = 0.f; }
    #pragma unroll
    for (int mi = 0; mi < 2; mi++) {
        int r0 = m0 + wm + mi * 16 + (lane >> 2);
        #pragma unroll
        for (int ni = 0; ni < 8; ni++) {
            int n = wn + ni * 8 + (lane & 3) * 2;
            float v0 = acc[mi][ni][0] + bb[ni].x;
            float v1 = acc[mi][ni][1] + bb[ni].y;
            float v2 = acc[mi][ni][2] + bb[ni].x;
            float v3 = acc[mi][ni][3] + bb[ni].y;
            *reinterpret_cast<float2*>(Y + (size_t)r0 * 128 + n) = make_float2(v0, v1);
            *reinterpret_cast<float2*>(Y + (size_t)(r0 + 8) * 128 + n) = make_float2(v2, v3);
            s[ni * 2 + 0] += v0 + v2;          s[ni * 2 + 1] += v1 + v3;
            q[ni * 2 + 0] += v0 * v0 + v2 * v2; q[ni * 2 + 1] += v1 * v1 + v3 * v3;
        }
    }
    stats_reduce(s, q, gsum, gss, wn, lane);
}

// -------- final BN+ReLU with inline coef compute --------
__global__ __launch_bounds__(256)
void bn_out_kernel(float* __restrict__ out,
                   const float* __restrict__ g1sum, const float* __restrict__ g1ss,
                   const float* __restrict__ gg, const float* __restrict__ be) {
    __shared__ float sa[128], sd[128];
    int tid = threadIdx.x;
    if (tid < 128) {
        float mu  = g1sum[tid] * INV_M;
        float var = g1ss[tid] * INV_M - mu * mu;
        float sc = gg[tid] * rsqrtf(var + BN_EPS_);
        sa[tid] = sc;
        sd[tid] = be[tid] - mu * sc;
    }
    __syncthreads();
    int i = blockIdx.x * 256 + tid;      // float4 index
    int c = (i * 4) & 127;
    float4 v = reinterpret_cast<float4*>(out)[i];
    v.x = fmaxf(sa[c + 0] * v.x + sd[c + 0], 0.f);
    v.y = fmaxf(sa[c + 1] * v.y + sd[c + 1], 0.f);
    v.z = fmaxf(sa[c + 2] * v.z + sd[c + 2], 0.f);
    v.w = fmaxf(sa[c + 3] * v.w + sd[c + 3], 0.f);
    reinterpret_cast<float4*>(out)[i] = v;
}

extern "C" void kernel_launch(void* const* d_in, const int* in_sizes, int n_in,
                              void* d_out, int out_size) {
    const float* xyz1  = (const float*)d_in[0];
    const float* xyz2  = (const float*)d_in[1];
    const float* feat1 = (const float*)d_in[2];
    const float* feat2 = (const float*)d_in[3];
    const float* w0    = (const float*)d_in[4];
    const float* b0    = (const float*)d_in[5];
    const float* gg0   = (const float*)d_in[6];
    const float* be0   = (const float*)d_in[7];
    const float* w1    = (const float*)d_in[8];
    const float* b1    = (const float*)d_in[9];
    const float* gg1   = (const float*)d_in[10];
    const float* be1   = (const float*)d_in[11];
    float* out = (float*)d_out;

    float *p_sum0, *p_ss0, *p_sum1, *p_ss1;
    __half *p_y1, *p_w0h, *p_w0l, *p_w1h, *p_w1l;
    cudaGetSymbolAddress((void**)&p_y1,   g_y1h);
    cudaGetSymbolAddress((void**)&p_w0h,  g_wt0h);
    cudaGetSymbolAddress((void**)&p_w0l,  g_wt0l);
    cudaGetSymbolAddress((void**)&p_w1h,  g_wt1h);
    cudaGetSymbolAddress((void**)&p_w1l,  g_wt1l);
    cudaGetSymbolAddress((void**)&p_sum0, g_sum0);
    cudaGetSymbolAddress((void**)&p_ss0,  g_ss0);
    cudaGetSymbolAddress((void**)&p_sum1, g_sum1);
    cudaGetSymbolAddress((void**)&p_ss1,  g_ss1);

    const int smem1 = 2 * STAGE_ + 3072;  // 113664 B (x2 CTA = 227328)
    const int smem2 = 2 * STAGE_ + 1024;  // 111616 B
    cudaFuncSetAttribute(gemm1_fused, cudaFuncAttributeMaxDynamicSharedMemorySize, smem1);
    cudaFuncSetAttribute(gemm2_mma,   cudaFuncAttributeMaxDynamicSharedMemorySize, smem2);

    knn_kernel<<<NPIX / 256, 256>>>(xyz1, xyz2);
    prep_kernel<<<(192 * 128 + 128 * 128 + 255) / 256, 256>>>(w0, w1);

    gemm1_fused<<<NPIX / 128, 256, smem1>>>(
        feat1, feat2, p_w0h, p_w0l, b0, p_y1, p_sum0, p_ss0);

    gemm2_mma<<<NPIX / 128, 256, smem2>>>(
        p_y1, p_w1h, p_w1l, b1, p_sum0, p_ss0, gg0, be0, out, p_sum1, p_ss1);

    bn_out_kernel<<<(NPIX * 128 / 4) / 256, 256>>>(out, p_sum1, p_ss1, gg1, be1);
}

// round 16
// speedup vs baseline: 1.7423x; 1.0172x over previous
#include <cuda_runtime.h>
#include <cuda_fp16.h>
#include <cstdint>

#define NPIX   131072          // B*H*W
#define NBATCH 65536           // H*W
#define HH_    64
#define WW_    1024
#define INV_M  (1.0f/131072.0f)
#define BN_EPS_ 1e-5f

// padded smem tile stride: 64 data + 8 pad elements -> 144B rows
#define LDS_    72
#define A_TILE  18432          // 128 * 72 * 2 bytes
#define STAGE_  55296          // 3 tiles (Ah, Bh, Bl)

__device__ __forceinline__ uint32_t smem_u32(const void* p) {
    uint32_t a;
    asm("{ .reg .u64 t; cvta.to.shared.u64 t, %1; cvt.u32.u64 %0, t; }" : "=r"(a) : "l"(p));
    return a;
}
__device__ __forceinline__ void cp16(uint32_t dst, const void* src) {
    asm volatile("cp.async.ca.shared.global [%0], [%1], 16;" :: "r"(dst), "l"(src));
}
#define CP_COMMIT() asm volatile("cp.async.commit_group;" ::: "memory")
#define CP_WAIT0()  asm volatile("cp.async.wait_group 0;" ::: "memory")

__device__ __forceinline__ void ldm_x4(uint32_t* r, uint32_t addr) {
    asm volatile("ldmatrix.sync.aligned.m8n8.x4.shared.b16 {%0,%1,%2,%3}, [%4];"
        : "=r"(r[0]), "=r"(r[1]), "=r"(r[2]), "=r"(r[3]) : "r"(addr));
}
__device__ __forceinline__ void mma_fp16(float* c, const uint32_t* a, const uint32_t* b) {
    asm volatile("mma.sync.aligned.m16n8k16.row.col.f32.f16.f16.f32 "
        "{%0,%1,%2,%3}, {%4,%5,%6,%7}, {%8,%9}, {%0,%1,%2,%3};"
        : "+f"(c[0]), "+f"(c[1]), "+f"(c[2]), "+f"(c[3])
        : "r"(a[0]), "r"(a[1]), "r"(a[2]), "r"(a[3]), "r"(b[0]), "r"(b[1]));
}

// -------- scratch (device globals; no allocs) --------
__device__ __half g_y1h[(size_t)NPIX * 128];
__device__ __half g_y2h[(size_t)NPIX * 128];
__device__ __half g_wt0h[3 * 128 * 64], g_wt0l[3 * 128 * 64];
__device__ __half g_wt1h[2 * 128 * 64], g_wt1l[2 * 128 * 64];
__device__ float g_sum0[128], g_ss0[128], g_sum1[128], g_ss1[128];
__device__ int   g_sel[NPIX * 3];
__device__ float g_coef[NPIX * 3];

// -------- grid KNN: first-3-valid in 5x5 window, inverse-distance coefs --------
__global__ void knn_kernel(const float* __restrict__ xyz1,
                           const float* __restrict__ xyz2) {
    int idx = blockIdx.x * blockDim.x + threadIdx.x;
    int b = idx >> 16;
    int n = idx & (NBATCH - 1);
    int h = n >> 10;
    int w = n & (WW_ - 1);

    const float* q = xyz1 + (size_t)idx * 3;
    float qx = q[0], qy = q[1], qz = q[2];

    int   sel[3] = {0, 0, 0};
    float mk[3]  = {0.f, 0.f, 0.f};
    int cnt = 0;

    #pragma unroll
    for (int dh = -2; dh <= 2; dh++) {
        int hh = h + dh;
        if (hh < 0 || hh >= HH_) continue;
        #pragma unroll
        for (int dw = -2; dw <= 2; dw++) {
            int ww = w + dw;
            if (ww < 0 || ww >= WW_) continue;
            int nn = (hh << 10) + ww;
            const float* p = xyz2 + ((size_t)b * NBATCH + nn) * 3;
            float dx = p[0] - qx, dy = p[1] - qy, dz = p[2] - qz;
            float d2 = dx * dx + dy * dy + dz * dz;
            if (d2 < 10000.0f && cnt < 3) { sel[cnt] = nn; mk[cnt] = 1.f; cnt++; }
        }
    }
    float inv[3]; float dsum = 0.f;
    #pragma unroll
    for (int s = 0; s < 3; s++) {
        const float* p = xyz2 + ((size_t)b * NBATCH + sel[s]) * 3;
        float gx = p[0] * mk[s], gy = p[1] * mk[s], gz = p[2] * mk[s];
        float dx = gx - qx, dy = gy - qy, dz = gz - qz;
        float d2 = dx * dx + dy * dy + dz * dz;
        if (d2 < 1e-10f) d2 = 1e-10f;
        inv[s] = 1.0f / d2;
        dsum += inv[s];
    }
    float rnorm = 1.0f / dsum;
    #pragma unroll
    for (int s = 0; s < 3; s++) {
        g_sel[idx * 3 + s]  = b * NBATCH + sel[s];
        g_coef[idx * 3 + s] = inv[s] * rnorm * mk[s];
    }
}

// -------- prep: both weight transposes (fp16 hi/lo) + zero stat accumulators --------
__global__ void prep_kernel(const float* __restrict__ w0, const float* __restrict__ w1) {
    int t = blockIdx.x * 256 + threadIdx.x;
    if (t < 128) {
        g_sum0[t] = 0.f; g_ss0[t] = 0.f;
        g_sum1[t] = 0.f; g_ss1[t] = 0.f;
    }
    if (t < 192 * 128) {
        int k = t >> 7, n = t & 127;
        float v = w0[t];
        __half h = __float2half(v);
        __half l = __float2half(v - __half2float(h));
        int o = ((k >> 6) * 128 + n) * 64 + (k & 63);
        g_wt0h[o] = h; g_wt0l[o] = l;
    } else {
        int t2 = t - 192 * 128;
        if (t2 < 128 * 128) {
            int k = t2 >> 7, n = t2 & 127;
            float v = w1[t2];
            __half h = __float2half(v);
            __half l = __float2half(v - __half2float(h));
            int o = ((k >> 6) * 128 + n) * 64 + (k & 63);
            g_wt1h[o] = h; g_wt1l[o] = l;
        }
    }
}

// -------- MMA on one chunk: batched x4 loads (A 2, Bh 4, Bl 4), then 32 HMMA/ks --------
// stage = [Ah | Bh | Bl]
__device__ __forceinline__ void mma_chunk(uint32_t sb, int lane, int wm, int wn,
                                          float (&acc)[2][8][4]) {
    #pragma unroll
    for (int ks = 0; ks < 4; ks++) {
        // batched fragment loads — all independent, latencies overlap
        uint32_t ah[2][4];
        {
            int col = ks * 16 + (lane >> 4) * 8;
            #pragma unroll
            for (int mi = 0; mi < 2; mi++) {
                int row = wm + mi * 16 + (lane & 15);
                ldm_x4(ah[mi], sb + (uint32_t)(row * LDS_ + col) * 2);
            }
        }
        uint32_t bh[4][4], bl[4][4];   // [pair p] covers ni = 2p, 2p+1
        {
            int row = (lane >> 4) * 8 + (lane & 7);          // 0..15 row-in-pair
            int col = ks * 16 + ((lane >> 3) & 1) * 8;
            uint32_t boff = (uint32_t)col * 2;
            #pragma unroll
            for (int p = 0; p < 4; p++) {
                uint32_t ro = (uint32_t)((wn + p * 16 + row) * LDS_) * 2 + boff;
                ldm_x4(bh[p], sb + A_TILE + ro);
                ldm_x4(bl[p], sb + 2 * A_TILE + ro);
            }
        }
        #pragma unroll
        for (int p = 0; p < 4; p++) {
            #pragma unroll
            for (int mi = 0; mi < 2; mi++) {
                mma_fp16(acc[mi][2 * p + 0], ah[mi], &bh[p][0]);
                mma_fp16(acc[mi][2 * p + 1], ah[mi], &bh[p][2]);
                mma_fp16(acc[mi][2 * p + 0], ah[mi], &bl[p][0]);
                mma_fp16(acc[mi][2 * p + 1], ah[mi], &bl[p][2]);
            }
        }
    }
}

// stats reduce + global atomics (shared by both epilogues)
__device__ __forceinline__ void stats_reduce(float (&s)[16], float (&q)[16],
        float* __restrict__ gsum, float* __restrict__ gss, int wn, int lane) {
    #pragma unroll
    for (int t = 0; t < 16; t++) {
        #pragma unroll
        for (int o = 4; o < 32; o <<= 1) {
            s[t] += __shfl_xor_sync(0xffffffffu, s[t], o);
            q[t] += __shfl_xor_sync(0xffffffffu, q[t], o);
        }
    }
    if (lane < 4) {
        #pragma unroll
        for (int ni = 0; ni < 8; ni++) {
            int col = wn + ni * 8 + lane * 2;
            atomicAdd(gsum + col,     s[ni * 2 + 0]);
            atomicAdd(gsum + col + 1, s[ni * 2 + 1]);
            atomicAdd(gss  + col,     q[ni * 2 + 0]);
            atomicAdd(gss  + col + 1, q[ni * 2 + 1]);
        }
    }
}

// fp32 float4 -> fp16, store 4 halves to stage A region
__device__ __forceinline__ void storeAh(const float4& v, char* smg, int stg,
                                        int row, int seg) {
    __half2 h01 = __floats2half2_rn(v.x, v.y);
    __half2 h23 = __floats2half2_rn(v.z, v.w);
    uint2 hv;
    hv.x = *reinterpret_cast<const uint32_t*>(&h01);
    hv.y = *reinterpret_cast<const uint32_t*>(&h23);
    *reinterpret_cast<uint2*>(smg + stg * STAGE_ + (uint32_t)(row * LDS_ + seg * 4) * 2) = hv;
}

// fp16 epilogue: bias add + half2 store + stats accumulation
__device__ __forceinline__ void epilogue_h(float (&acc)[2][8][4],
        const float* __restrict__ bias, __half* __restrict__ Y,
        float* __restrict__ gsum, float* __restrict__ gss,
        int m0, int wm, int wn, int lane) {
    float2 bb[8];
    #pragma unroll
    for (int ni = 0; ni < 8; ni++) {
        int n = wn + ni * 8 + (lane & 3) * 2;
        bb[ni].x = __ldg(bias + n);
        bb[ni].y = __ldg(bias + n + 1);
    }
    float s[16], q[16];
    #pragma unroll
    for (int t = 0; t < 16; t++) { s[t] = 0.f; q[t] = 0.f; }
    #pragma unroll
    for (int mi = 0; mi < 2; mi++) {
        int r0 = m0 + wm + mi * 16 + (lane >> 2);
        #pragma unroll
        for (int ni = 0; ni < 8; ni++) {
            int n = wn + ni * 8 + (lane & 3) * 2;
            float v0 = acc[mi][ni][0] + bb[ni].x;
            float v1 = acc[mi][ni][1] + bb[ni].y;
            float v2 = acc[mi][ni][2] + bb[ni].x;
            float v3 = acc[mi][ni][3] + bb[ni].y;
            *reinterpret_cast<__half2*>(Y + (size_t)r0 * 128 + n) = __floats2half2_rn(v0, v1);
            *reinterpret_cast<__half2*>(Y + (size_t)(r0 + 8) * 128 + n) = __floats2half2_rn(v2, v3);
            s[ni * 2 + 0] += v0 + v2;          s[ni * 2 + 1] += v1 + v3;
            q[ni * 2 + 0] += v0 * v0 + v2 * v2; q[ni * 2 + 1] += v1 * v1 + v3 * v3;
        }
    }
    stats_reduce(s, q, gsum, gss, wn, lane);
}

// -------- GEMM1: fused gather/interp/concat A-build, fp16 y1 out, fused stats --------
__global__ __launch_bounds__(256, 2)
void gemm1_fused(const float* __restrict__ feat1,
                 const float* __restrict__ feat2,
                 const __half* __restrict__ Bh,
                 const __half* __restrict__ Bl,
                 const float* __restrict__ bias,
                 __half* __restrict__ Y,
                 float* __restrict__ gsum, float* __restrict__ gss) {
    extern __shared__ __align__(16) char smg[];
    const uint32_t sbase = smem_u32(smg);
    int*   ssel  = reinterpret_cast<int*>(smg + 2 * STAGE_);
    float* scoef = reinterpret_cast<float*>(smg + 2 * STAGE_ + 1536);
    const int tid = threadIdx.x, lane = tid & 31, wid = tid >> 5;
    const int m0 = blockIdx.x * 128;
    const int wm = (wid & 3) * 32, wn = (wid >> 2) * 64;

    float acc[2][8][4];
    #pragma unroll
    for (int mi = 0; mi < 2; mi++)
        #pragma unroll
        for (int ni = 0; ni < 8; ni++)
            #pragma unroll
            for (int j = 0; j < 4; j++) acc[mi][ni][j] = 0.f;

    auto loadB = [&](int c, int stg) {
        uint32_t sb = sbase + stg * STAGE_;
        #pragma unroll
        for (int i = 0; i < 4; i++) {
            int u = i * 256 + tid, row = u >> 3, seg = u & 7;
            uint32_t so = (uint32_t)(row * LDS_ + seg * 8) * 2;
            int gb = c * 8192 + row * 64 + seg * 8;
            cp16(sb + A_TILE + so, Bh + gb);
            cp16(sb + 2 * A_TILE + so, Bl + gb);
        }
        CP_COMMIT();
    };
    auto gatherA = [&](int stg, int half) {
        #pragma unroll
        for (int i = 0; i < 8; i++) {
            int u = i * 256 + tid, row = u >> 4, seg = u & 15;
            int   s0 = ssel[row * 3 + 0], s1 = ssel[row * 3 + 1], s2 = ssel[row * 3 + 2];
            float c0 = scoef[row * 3 + 0], c1 = scoef[row * 3 + 1], c2 = scoef[row * 3 + 2];
            int off = half * 64 + seg * 4;
            float4 a = *reinterpret_cast<const float4*>(feat2 + (size_t)s0 * 128 + off);
            float4 b = *reinterpret_cast<const float4*>(feat2 + (size_t)s1 * 128 + off);
            float4 c = *reinterpret_cast<const float4*>(feat2 + (size_t)s2 * 128 + off);
            float4 r;
            r.x = c0 * a.x + c1 * b.x + c2 * c.x;
            r.y = c0 * a.y + c1 * b.y + c2 * c.y;
            r.z = c0 * a.z + c1 * b.z + c2 * c.z;
            r.w = c0 * a.w + c1 * b.w + c2 * c.w;
            storeAh(r, smg, stg, row, seg);
        }
    };

    // stage sel/coef for the block's 128 pixels
    for (int t = tid; t < 384; t += 256) {
        ssel[t]  = g_sel[(size_t)m0 * 3 + t];
        scoef[t] = g_coef[(size_t)m0 * 3 + t];
    }
    // chunk 0 A = feat1 (direct)
    #pragma unroll
    for (int i = 0; i < 8; i++) {
        int u = i * 256 + tid, row = u >> 4, seg = u & 15;
        float4 v = *reinterpret_cast<const float4*>(
            feat1 + (size_t)(m0 + row) * 64 + seg * 4);
        storeAh(v, smg, 0, row, seg);
    }
    loadB(0, 0);
    loadB(1, 1);
    __syncthreads();            // ssel/scoef visible
    gatherA(1, 0);              // chunk-1 A -> stage 1
    CP_WAIT0(); __syncthreads();

    mma_chunk(sbase, lane, wm, wn, acc);              // chunk 0
    __syncthreads();
    loadB(2, 0);                                      // async B2 -> s0
    gatherA(0, 1);                                    // chunk-2 A -> s0
    mma_chunk(sbase + STAGE_, lane, wm, wn, acc);     // chunk 1 (overlaps B2)
    CP_WAIT0(); __syncthreads();
    mma_chunk(sbase, lane, wm, wn, acc);              // chunk 2

    epilogue_h(acc, bias, Y, gsum, gss, m0, wm, wn, lane);
}

// -------- GEMM2: fp16 y1 in, inline BN-coef + BN+ReLU, fp16 y2 out, fused stats ----
__global__ __launch_bounds__(256, 2)
void gemm2_mma(const __half* __restrict__ Ah,
               const __half* __restrict__ Bh,
               const __half* __restrict__ Bl,
               const float* __restrict__ bias,
               const float* __restrict__ g0sum, const float* __restrict__ g0ss,
               const float* __restrict__ gg, const float* __restrict__ be,
               __half* __restrict__ Y,
               float* __restrict__ gsum, float* __restrict__ gss) {
    extern __shared__ __align__(16) char smg[];
    const uint32_t sbase = smem_u32(smg);
    float* sa = reinterpret_cast<float*>(smg + 2 * STAGE_);
    float* sd = sa + 128;
    const int tid = threadIdx.x, lane = tid & 31, wid = tid >> 5;
    const int m0 = blockIdx.x * 128;
    const int wm = (wid & 3) * 32, wn = (wid >> 2) * 64;

    // inline finalize of layer-0 BN coefs
    if (tid < 128) {
        float mu  = g0sum[tid] * INV_M;
        float var = g0ss[tid] * INV_M - mu * mu;
        float sc = gg[tid] * rsqrtf(var + BN_EPS_);
        sa[tid] = sc;
        sd[tid] = be[tid] - mu * sc;
    }

    float acc[2][8][4];
    #pragma unroll
    for (int mi = 0; mi < 2; mi++)
        #pragma unroll
        for (int ni = 0; ni < 8; ni++)
            #pragma unroll
            for (int j = 0; j < 4; j++) acc[mi][ni][j] = 0.f;

    auto loadB = [&](int c, int stg) {
        uint32_t sb = sbase + stg * STAGE_;
        #pragma unroll
        for (int i = 0; i < 4; i++) {
            int u = i * 256 + tid, row = u >> 3, seg = u & 7;
            uint32_t so = (uint32_t)(row * LDS_ + seg * 8) * 2;
            int gb = c * 8192 + row * 64 + seg * 8;
            cp16(sb + A_TILE + so, Bh + gb);
            cp16(sb + 2 * A_TILE + so, Bl + gb);
        }
        CP_COMMIT();
    };

    loadB(0, 0);
    loadB(1, 1);
    __syncthreads();            // sa/sd visible

    // A chunks: read fp16 y1, BN+ReLU, restore fp16 (8 halves/thread/iter)
    #pragma unroll
    for (int c = 0; c < 2; c++) {
        #pragma unroll
        for (int i = 0; i < 4; i++) {
            int u = i * 256 + tid, row = u >> 3, seg = u & 7;   // 8 segs x 8 halves
            uint4 raw = *reinterpret_cast<const uint4*>(
                Ah + (size_t)(m0 + row) * 128 + c * 64 + seg * 8);
            const __half2* hp = reinterpret_cast<const __half2*>(&raw);
            uint4 outv;
            __half2* op = reinterpret_cast<__half2*>(&outv);
            #pragma unroll
            for (int j = 0; j < 4; j++) {
                float2 f = __half22float2(hp[j]);
                int k = c * 64 + seg * 8 + j * 2;
                f.x = fmaxf(sa[k] * f.x + sd[k], 0.f);
                f.y = fmaxf(sa[k + 1] * f.y + sd[k + 1], 0.f);
                op[j] = __floats2half2_rn(f.x, f.y);
            }
            *reinterpret_cast<uint4*>(smg + c * STAGE_ +
                (uint32_t)(row * LDS_ + seg * 8) * 2) = outv;
        }
    }
    CP_WAIT0(); __syncthreads();

    mma_chunk(sbase, lane, wm, wn, acc);
    mma_chunk(sbase + STAGE_, lane, wm, wn, acc);

    epilogue_h(acc, bias, Y, gsum, gss, m0, wm, wn, lane);
}

// -------- final BN+ReLU: fp16 y2 in, fp32 out, inline coef compute --------
__global__ __launch_bounds__(256)
void bn_out_kernel(const __half* __restrict__ y2, float* __restrict__ out,
                   const float* __restrict__ g1sum, const float* __restrict__ g1ss,
                   const float* __restrict__ gg, const float* __restrict__ be) {
    __shared__ float sa[128], sd[128];
    int tid = threadIdx.x;
    if (tid < 128) {
        float mu  = g1sum[tid] * INV_M;
        float var = g1ss[tid] * INV_M - mu * mu;
        float sc = gg[tid] * rsqrtf(var + BN_EPS_);
        sa[tid] = sc;
        sd[tid] = be[tid] - mu * sc;
    }
    __syncthreads();
    int i = blockIdx.x * 256 + tid;      // group of 4 elements
    int c = (i * 4) & 127;
    uint2 raw = *reinterpret_cast<const uint2*>(y2 + (size_t)i * 4);
    const __half2* hp = reinterpret_cast<const __half2*>(&raw);
    float2 f0 = __half22float2(hp[0]);
    float2 f1 = __half22float2(hp[1]);
    float4 v;
    v.x = fmaxf(sa[c + 0] * f0.x + sd[c + 0], 0.f);
    v.y = fmaxf(sa[c + 1] * f0.y + sd[c + 1], 0.f);
    v.z = fmaxf(sa[c + 2] * f1.x + sd[c + 2], 0.f);
    v.w = fmaxf(sa[c + 3] * f1.y + sd[c + 3], 0.f);
    reinterpret_cast<float4*>(out)[i] = v;
}

extern "C" void kernel_launch(void* const* d_in, const int* in_sizes, int n_in,
                              void* d_out, int out_size) {
    const float* xyz1  = (const float*)d_in[0];
    const float* xyz2  = (const float*)d_in[1];
    const float* feat1 = (const float*)d_in[2];
    const float* feat2 = (const float*)d_in[3];
    const float* w0    = (const float*)d_in[4];
    const float* b0    = (const float*)d_in[5];
    const float* gg0   = (const float*)d_in[6];
    const float* be0   = (const float*)d_in[7];
    const float* w1    = (const float*)d_in[8];
    const float* b1    = (const float*)d_in[9];
    const float* gg1   = (const float*)d_in[10];
    const float* be1   = (const float*)d_in[11];
    float* out = (float*)d_out;

    float *p_sum0, *p_ss0, *p_sum1, *p_ss1;
    __half *p_y1, *p_y2, *p_w0h, *p_w0l, *p_w1h, *p_w1l;
    cudaGetSymbolAddress((void**)&p_y1,   g_y1h);
    cudaGetSymbolAddress((void**)&p_y2,   g_y2h);
    cudaGetSymbolAddress((void**)&p_w0h,  g_wt0h);
    cudaGetSymbolAddress((void**)&p_w0l,  g_wt0l);
    cudaGetSymbolAddress((void**)&p_w1h,  g_wt1h);
    cudaGetSymbolAddress((void**)&p_w1l,  g_wt1l);
    cudaGetSymbolAddress((void**)&p_sum0, g_sum0);
    cudaGetSymbolAddress((void**)&p_ss0,  g_ss0);
    cudaGetSymbolAddress((void**)&p_sum1, g_sum1);
    cudaGetSymbolAddress((void**)&p_ss1,  g_ss1);

    const int smem1 = 2 * STAGE_ + 3072;  // 113664 B (x2 CTA = 227328)
    const int smem2 = 2 * STAGE_ + 1024;  // 111616 B
    cudaFuncSetAttribute(gemm1_fused, cudaFuncAttributeMaxDynamicSharedMemorySize, smem1);
    cudaFuncSetAttribute(gemm2_mma,   cudaFuncAttributeMaxDynamicSharedMemorySize, smem2);

    knn_kernel<<<NPIX / 256, 256>>>(xyz1, xyz2);
    prep_kernel<<<(192 * 128 + 128 * 128 + 255) / 256, 256>>>(w0, w1);

    gemm1_fused<<<NPIX / 128, 256, smem1>>>(
        feat1, feat2, p_w0h, p_w0l, b0, p_y1, p_sum0, p_ss0);

    gemm2_mma<<<NPIX / 128, 256, smem2>>>(
        p_y1, p_w1h, p_w1l, b1, p_sum0, p_ss0, gg0, be0, p_y2, p_sum1, p_ss1);

    bn_out_kernel<<<(NPIX * 128 / 4) / 256, 256>>>(p_y2, out, p_sum1, p_ss1, gg1, be1);
}

// round 17
// speedup vs baseline: 1.7602x; 1.0102x over previous
#include <cuda_runtime.h>
#include <cuda_fp16.h>
#include <cstdint>

#define NPIX   131072          // B*H*W
#define NBATCH 65536           // H*W
#define HH_    64
#define WW_    1024
#define INV_M  (1.0f/131072.0f)
#define BN_EPS_ 1e-5f

// padded smem tile stride: 64 data + 8 pad halves -> 144B rows
#define LDS_    72
#define T_TILE  9216           // 64 * 72 * 2 bytes (one 64-row tile)
#define B_OFF_H 9216
#define B_OFF_L 18432
#define STAGE_  27648          // [A | Bh | Bl]

__device__ __forceinline__ uint32_t smem_u32(const void* p) {
    uint32_t a;
    asm("{ .reg .u64 t; cvta.to.shared.u64 t, %1; cvt.u32.u64 %0, t; }" : "=r"(a) : "l"(p));
    return a;
}
__device__ __forceinline__ void cp16(uint32_t dst, const void* src) {
    asm volatile("cp.async.ca.shared.global [%0], [%1], 16;" :: "r"(dst), "l"(src));
}
#define CP_COMMIT() asm volatile("cp.async.commit_group;" ::: "memory")
#define CP_WAIT0()  asm volatile("cp.async.wait_group 0;" ::: "memory")

__device__ __forceinline__ void ldm_x4(uint32_t* r, uint32_t addr) {
    asm volatile("ldmatrix.sync.aligned.m8n8.x4.shared.b16 {%0,%1,%2,%3}, [%4];"
        : "=r"(r[0]), "=r"(r[1]), "=r"(r[2]), "=r"(r[3]) : "r"(addr));
}
__device__ __forceinline__ void mma_fp16(float* c, const uint32_t* a, const uint32_t* b) {
    asm volatile("mma.sync.aligned.m16n8k16.row.col.f32.f16.f16.f32 "
        "{%0,%1,%2,%3}, {%4,%5,%6,%7}, {%8,%9}, {%0,%1,%2,%3};"
        : "+f"(c[0]), "+f"(c[1]), "+f"(c[2]), "+f"(c[3])
        : "r"(a[0]), "r"(a[1]), "r"(a[2]), "r"(a[3]), "r"(b[0]), "r"(b[1]));
}

// -------- scratch (device globals; no allocs) --------
__device__ __half g_y1h[(size_t)NPIX * 128];
__device__ __half g_y2h[(size_t)NPIX * 128];
__device__ __half g_wt0h[3 * 128 * 64], g_wt0l[3 * 128 * 64];
__device__ __half g_wt1h[2 * 128 * 64], g_wt1l[2 * 128 * 64];
__device__ float g_sum0[128], g_ss0[128], g_sum1[128], g_ss1[128];
__device__ int   g_sel[NPIX * 3];
__device__ float g_coef[NPIX * 3];

// -------- grid KNN: first-3-valid in 5x5 window, inverse-distance coefs --------
__global__ void knn_kernel(const float* __restrict__ xyz1,
                           const float* __restrict__ xyz2) {
    int idx = blockIdx.x * blockDim.x + threadIdx.x;
    int b = idx >> 16;
    int n = idx & (NBATCH - 1);
    int h = n >> 10;
    int w = n & (WW_ - 1);

    const float* q = xyz1 + (size_t)idx * 3;
    float qx = q[0], qy = q[1], qz = q[2];

    int   sel[3] = {0, 0, 0};
    float mk[3]  = {0.f, 0.f, 0.f};
    int cnt = 0;

    #pragma unroll
    for (int dh = -2; dh <= 2; dh++) {
        int hh = h + dh;
        if (hh < 0 || hh >= HH_) continue;
        #pragma unroll
        for (int dw = -2; dw <= 2; dw++) {
            int ww = w + dw;
            if (ww < 0 || ww >= WW_) continue;
            int nn = (hh << 10) + ww;
            const float* p = xyz2 + ((size_t)b * NBATCH + nn) * 3;
            float dx = p[0] - qx, dy = p[1] - qy, dz = p[2] - qz;
            float d2 = dx * dx + dy * dy + dz * dz;
            if (d2 < 10000.0f && cnt < 3) { sel[cnt] = nn; mk[cnt] = 1.f; cnt++; }
        }
    }
    float inv[3]; float dsum = 0.f;
    #pragma unroll
    for (int s = 0; s < 3; s++) {
        const float* p = xyz2 + ((size_t)b * NBATCH + sel[s]) * 3;
        float gx = p[0] * mk[s], gy = p[1] * mk[s], gz = p[2] * mk[s];
        float dx = gx - qx, dy = gy - qy, dz = gz - qz;
        float d2 = dx * dx + dy * dy + dz * dz;
        if (d2 < 1e-10f) d2 = 1e-10f;
        inv[s] = 1.0f / d2;
        dsum += inv[s];
    }
    float rnorm = 1.0f / dsum;
    #pragma unroll
    for (int s = 0; s < 3; s++) {
        g_sel[idx * 3 + s]  = b * NBATCH + sel[s];
        g_coef[idx * 3 + s] = inv[s] * rnorm * mk[s];
    }
}

// -------- prep: both weight transposes (fp16 hi/lo) + zero stat accumulators --------
__global__ void prep_kernel(const float* __restrict__ w0, const float* __restrict__ w1) {
    int t = blockIdx.x * 256 + threadIdx.x;
    if (t < 128) {
        g_sum0[t] = 0.f; g_ss0[t] = 0.f;
        g_sum1[t] = 0.f; g_ss1[t] = 0.f;
    }
    if (t < 192 * 128) {
        int k = t >> 7, n = t & 127;
        float v = w0[t];
        __half h = __float2half(v);
        __half l = __float2half(v - __half2float(h));
        int o = ((k >> 6) * 128 + n) * 64 + (k & 63);
        g_wt0h[o] = h; g_wt0l[o] = l;
    } else {
        int t2 = t - 192 * 128;
        if (t2 < 128 * 128) {
            int k = t2 >> 7, n = t2 & 127;
            float v = w1[t2];
            __half h = __float2half(v);
            __half l = __float2half(v - __half2float(h));
            int o = ((k >> 6) * 128 + n) * 64 + (k & 63);
            g_wt1h[o] = h; g_wt1l[o] = l;
        }
    }
}

// -------- MMA on one chunk: 32x32 warp tile, batched x4 loads --------
// stage = [A(64xLDS_) | Bh(64xLDS_) | Bl(64xLDS_)]
__device__ __forceinline__ void mma_chunk(uint32_t sb, int lane, int wm, int wn,
                                          float (&acc)[2][4][4]) {
    #pragma unroll
    for (int ks = 0; ks < 4; ks++) {
        uint32_t ah[2][4];
        int colA = ks * 16 + (lane >> 4) * 8;
        #pragma unroll
        for (int mi = 0; mi < 2; mi++) {
            int row = wm + mi * 16 + (lane & 15);
            ldm_x4(ah[mi], sb + (uint32_t)(row * LDS_ + colA) * 2);
        }
        uint32_t bh[2][4], bl[2][4];       // pair p covers ni = 2p, 2p+1
        int rowb = (lane >> 4) * 8 + (lane & 7);
        int colb = ks * 16 + ((lane >> 3) & 1) * 8;
        #pragma unroll
        for (int p = 0; p < 2; p++) {
            uint32_t ro = (uint32_t)((wn + p * 16 + rowb) * LDS_ + colb) * 2;
            ldm_x4(bh[p], sb + B_OFF_H + ro);
            ldm_x4(bl[p], sb + B_OFF_L + ro);
        }
        #pragma unroll
        for (int p = 0; p < 2; p++) {
            #pragma unroll
            for (int mi = 0; mi < 2; mi++) {
                mma_fp16(acc[mi][2 * p + 0], ah[mi], &bh[p][0]);
                mma_fp16(acc[mi][2 * p + 1], ah[mi], &bh[p][2]);
                mma_fp16(acc[mi][2 * p + 0], ah[mi], &bl[p][0]);
                mma_fp16(acc[mi][2 * p + 1], ah[mi], &bl[p][2]);
            }
        }
    }
}

// fp32 float4 -> fp16, store 4 halves into stage A region
__device__ __forceinline__ void storeAh(const float4& v, char* smg, uint32_t stgoff,
                                        int row, int seg) {
    __half2 h01 = __floats2half2_rn(v.x, v.y);
    __half2 h23 = __floats2half2_rn(v.z, v.w);
    uint2 hv;
    hv.x = *reinterpret_cast<const uint32_t*>(&h01);
    hv.y = *reinterpret_cast<const uint32_t*>(&h23);
    *reinterpret_cast<uint2*>(smg + stgoff + (uint32_t)(row * LDS_ + seg * 4) * 2) = hv;
}

// fp16 epilogue: bias add + half2 store + per-channel stats
__device__ __forceinline__ void epilogue_h(float (&acc)[2][4][4],
        const float* __restrict__ bias, __half* __restrict__ Y,
        float* __restrict__ gsum, float* __restrict__ gss,
        int m0, int n0, int wm, int wn, int lane) {
    float2 bb[4];
    #pragma unroll
    for (int ni = 0; ni < 4; ni++) {
        int n = n0 + wn + ni * 8 + (lane & 3) * 2;
        bb[ni].x = __ldg(bias + n);
        bb[ni].y = __ldg(bias + n + 1);
    }
    float s[8], q[8];
    #pragma unroll
    for (int t = 0; t < 8; t++) { s[t] = 0.f; q[t] = 0.f; }
    #pragma unroll
    for (int mi = 0; mi < 2; mi++) {
        int r0 = m0 + wm + mi * 16 + (lane >> 2);
        #pragma unroll
        for (int ni = 0; ni < 4; ni++) {
            int n = n0 + wn + ni * 8 + (lane & 3) * 2;
            float v0 = acc[mi][ni][0] + bb[ni].x;
            float v1 = acc[mi][ni][1] + bb[ni].y;
            float v2 = acc[mi][ni][2] + bb[ni].x;
            float v3 = acc[mi][ni][3] + bb[ni].y;
            *reinterpret_cast<__half2*>(Y + (size_t)r0 * 128 + n) = __floats2half2_rn(v0, v1);
            *reinterpret_cast<__half2*>(Y + (size_t)(r0 + 8) * 128 + n) = __floats2half2_rn(v2, v3);
            s[ni * 2 + 0] += v0 + v2;          s[ni * 2 + 1] += v1 + v3;
            q[ni * 2 + 0] += v0 * v0 + v2 * v2; q[ni * 2 + 1] += v1 * v1 + v3 * v3;
        }
    }
    #pragma unroll
    for (int t = 0; t < 8; t++) {
        #pragma unroll
        for (int o = 4; o < 32; o <<= 1) {
            s[t] += __shfl_xor_sync(0xffffffffu, s[t], o);
            q[t] += __shfl_xor_sync(0xffffffffu, q[t], o);
        }
    }
    if (lane < 4) {
        #pragma unroll
        for (int ni = 0; ni < 4; ni++) {
            int col = n0 + wn + ni * 8 + lane * 2;
            atomicAdd(gsum + col,     s[ni * 2 + 0]);
            atomicAdd(gsum + col + 1, s[ni * 2 + 1]);
            atomicAdd(gss  + col,     q[ni * 2 + 0]);
            atomicAdd(gss  + col + 1, q[ni * 2 + 1]);
        }
    }
}

// -------- GEMM1: 64x64 tiles, fused gather A-build, fp16 y1 out, fused stats --------
__global__ __launch_bounds__(128, 4)
void gemm1_fused(const float* __restrict__ feat1,
                 const float* __restrict__ feat2,
                 const __half* __restrict__ Bh,
                 const __half* __restrict__ Bl,
                 const float* __restrict__ bias,
                 __half* __restrict__ Y,
                 float* __restrict__ gsum, float* __restrict__ gss) {
    extern __shared__ __align__(16) char smg[];
    const uint32_t sbase = smem_u32(smg);
    int*   ssel  = reinterpret_cast<int*>(smg + 2 * STAGE_);
    float* scoef = reinterpret_cast<float*>(smg + 2 * STAGE_ + 768);
    const int tid = threadIdx.x, lane = tid & 31, wid = tid >> 5;
    const int m0 = (blockIdx.x >> 1) * 64;
    const int n0 = (blockIdx.x & 1) * 64;
    const int wm = (wid & 1) * 32, wn = (wid >> 1) * 32;

    float acc[2][4][4];
    #pragma unroll
    for (int mi = 0; mi < 2; mi++)
        #pragma unroll
        for (int ni = 0; ni < 4; ni++)
            #pragma unroll
            for (int j = 0; j < 4; j++) acc[mi][ni][j] = 0.f;

    auto loadB = [&](int c, int stg) {
        uint32_t sb = sbase + stg * STAGE_;
        #pragma unroll
        for (int i = 0; i < 4; i++) {
            int u = i * 128 + tid, row = u >> 3, seg = u & 7;
            uint32_t so = (uint32_t)(row * LDS_ + seg * 8) * 2;
            int gb = c * 8192 + (n0 + row) * 64 + seg * 8;
            cp16(sb + B_OFF_H + so, Bh + gb);
            cp16(sb + B_OFF_L + so, Bl + gb);
        }
        CP_COMMIT();
    };
    auto gatherA = [&](int stg, int half) {
        #pragma unroll
        for (int i = 0; i < 8; i++) {
            int u = i * 128 + tid, row = u >> 4, seg = u & 15;
            int   s0 = ssel[row * 3 + 0], s1 = ssel[row * 3 + 1], s2 = ssel[row * 3 + 2];
            float c0 = scoef[row * 3 + 0], c1 = scoef[row * 3 + 1], c2 = scoef[row * 3 + 2];
            int off = half * 64 + seg * 4;
            float4 a = *reinterpret_cast<const float4*>(feat2 + (size_t)s0 * 128 + off);
            float4 b = *reinterpret_cast<const float4*>(feat2 + (size_t)s1 * 128 + off);
            float4 c = *reinterpret_cast<const float4*>(feat2 + (size_t)s2 * 128 + off);
            float4 r;
            r.x = c0 * a.x + c1 * b.x + c2 * c.x;
            r.y = c0 * a.y + c1 * b.y + c2 * c.y;
            r.z = c0 * a.z + c1 * b.z + c2 * c.z;
            r.w = c0 * a.w + c1 * b.w + c2 * c.w;
            storeAh(r, smg, (uint32_t)stg * STAGE_, row, seg);
        }
    };

    // stage sel/coef for this tile's 64 pixels (192 entries)
    for (int t = tid; t < 192; t += 128) {
        ssel[t]  = g_sel[(size_t)m0 * 3 + t];
        scoef[t] = g_coef[(size_t)m0 * 3 + t];
    }
    // chunk 0 A = feat1 (direct): 64 rows x 16 float4
    #pragma unroll
    for (int i = 0; i < 8; i++) {
        int u = i * 128 + tid, row = u >> 4, seg = u & 15;
        float4 v = *reinterpret_cast<const float4*>(
            feat1 + (size_t)(m0 + row) * 64 + seg * 4);
        storeAh(v, smg, 0, row, seg);
    }
    loadB(0, 0);
    loadB(1, 1);
    __syncthreads();                 // sel/coef + A0 visible
    gatherA(1, 0);                   // chunk-1 A -> stage 1
    CP_WAIT0(); __syncthreads();

    mma_chunk(sbase, lane, wm, wn, acc);              // chunk 0
    __syncthreads();                                  // all done reading s0
    loadB(2, 0);                                      // async B2 -> s0
    gatherA(0, 1);                                    // chunk-2 A -> s0
    mma_chunk(sbase + STAGE_, lane, wm, wn, acc);     // chunk 1
    CP_WAIT0(); __syncthreads();
    mma_chunk(sbase, lane, wm, wn, acc);              // chunk 2

    epilogue_h(acc, bias, Y, gsum, gss, m0, n0, wm, wn, lane);
}

// -------- GEMM2: 64x64 tiles, fp16 y1 in, inline BN+ReLU, fp16 y2 out, stats ----
__global__ __launch_bounds__(128, 4)
void gemm2_mma(const __half* __restrict__ Ah,
               const __half* __restrict__ Bh,
               const __half* __restrict__ Bl,
               const float* __restrict__ bias,
               const float* __restrict__ g0sum, const float* __restrict__ g0ss,
               const float* __restrict__ gg, const float* __restrict__ be,
               __half* __restrict__ Y,
               float* __restrict__ gsum, float* __restrict__ gss) {
    extern __shared__ __align__(16) char smg[];
    const uint32_t sbase = smem_u32(smg);
    float* sa = reinterpret_cast<float*>(smg + 2 * STAGE_);
    float* sd = sa + 128;
    const int tid = threadIdx.x, lane = tid & 31, wid = tid >> 5;
    const int m0 = (blockIdx.x >> 1) * 64;
    const int n0 = (blockIdx.x & 1) * 64;
    const int wm = (wid & 1) * 32, wn = (wid >> 1) * 32;

    // inline finalize of layer-0 BN coefs (128 threads -> 128 channels)
    {
        float mu  = g0sum[tid] * INV_M;
        float var = g0ss[tid] * INV_M - mu * mu;
        float sc = gg[tid] * rsqrtf(var + BN_EPS_);
        sa[tid] = sc;
        sd[tid] = be[tid] - mu * sc;
    }

    float acc[2][4][4];
    #pragma unroll
    for (int mi = 0; mi < 2; mi++)
        #pragma unroll
        for (int ni = 0; ni < 4; ni++)
            #pragma unroll
            for (int j = 0; j < 4; j++) acc[mi][ni][j] = 0.f;

    auto loadB = [&](int c, int stg) {
        uint32_t sb = sbase + stg * STAGE_;
        #pragma unroll
        for (int i = 0; i < 4; i++) {
            int u = i * 128 + tid, row = u >> 3, seg = u & 7;
            uint32_t so = (uint32_t)(row * LDS_ + seg * 8) * 2;
            int gb = c * 8192 + (n0 + row) * 64 + seg * 8;
            cp16(sb + B_OFF_H + so, Bh + gb);
            cp16(sb + B_OFF_L + so, Bl + gb);
        }
        CP_COMMIT();
    };

    loadB(0, 0);
    loadB(1, 1);
    __syncthreads();            // sa/sd visible

    // A chunks: read fp16 y1, BN+ReLU, store fp16 to stage A (both chunks upfront)
    #pragma unroll
    for (int c = 0; c < 2; c++) {
        #pragma unroll
        for (int i = 0; i < 4; i++) {
            int u = i * 128 + tid, row = u >> 3, seg = u & 7;   // 8 segs x 8 halves
            uint4 raw = *reinterpret_cast<const uint4*>(
                Ah + (size_t)(m0 + row) * 128 + c * 64 + seg * 8);
            const __half2* hp = reinterpret_cast<const __half2*>(&raw);
            uint4 outv;
            __half2* op = reinterpret_cast<__half2*>(&outv);
            #pragma unroll
            for (int j = 0; j < 4; j++) {
                float2 f = __half22float2(hp[j]);
                int k = c * 64 + seg * 8 + j * 2;
                f.x = fmaxf(sa[k] * f.x + sd[k], 0.f);
                f.y = fmaxf(sa[k + 1] * f.y + sd[k + 1], 0.f);
                op[j] = __floats2half2_rn(f.x, f.y);
            }
            *reinterpret_cast<uint4*>(smg + c * STAGE_ +
                (uint32_t)(row * LDS_ + seg * 8) * 2) = outv;
        }
    }
    CP_WAIT0(); __syncthreads();

    mma_chunk(sbase, lane, wm, wn, acc);
    mma_chunk(sbase + STAGE_, lane, wm, wn, acc);

    epilogue_h(acc, bias, Y, gsum, gss, m0, n0, wm, wn, lane);
}

// -------- final BN+ReLU: fp16 y2 in, fp32 out, inline coef compute --------
__global__ __launch_bounds__(256)
void bn_out_kernel(const __half* __restrict__ y2, float* __restrict__ out,
                   const float* __restrict__ g1sum, const float* __restrict__ g1ss,
                   const float* __restrict__ gg, const float* __restrict__ be) {
    __shared__ float sa[128], sd[128];
    int tid = threadIdx.x;
    if (tid < 128) {
        float mu  = g1sum[tid] * INV_M;
        float var = g1ss[tid] * INV_M - mu * mu;
        float sc = gg[tid] * rsqrtf(var + BN_EPS_);
        sa[tid] = sc;
        sd[tid] = be[tid] - mu * sc;
    }
    __syncthreads();
    int i = blockIdx.x * 256 + tid;      // group of 4 elements
    int c = (i * 4) & 127;
    uint2 raw = *reinterpret_cast<const uint2*>(y2 + (size_t)i * 4);
    const __half2* hp = reinterpret_cast<const __half2*>(&raw);
    float2 f0 = __half22float2(hp[0]);
    float2 f1 = __half22float2(hp[1]);
    float4 v;
    v.x = fmaxf(sa[c + 0] * f0.x + sd[c + 0], 0.f);
    v.y = fmaxf(sa[c + 1] * f0.y + sd[c + 1], 0.f);
    v.z = fmaxf(sa[c + 2] * f1.x + sd[c + 2], 0.f);
    v.w = fmaxf(sa[c + 3] * f1.y + sd[c + 3], 0.f);
    reinterpret_cast<float4*>(out)[i] = v;
}

extern "C" void kernel_launch(void* const* d_in, const int* in_sizes, int n_in,
                              void* d_out, int out_size) {
    const float* xyz1  = (const float*)d_in[0];
    const float* xyz2  = (const float*)d_in[1];
    const float* feat1 = (const float*)d_in[2];
    const float* feat2 = (const float*)d_in[3];
    const float* w0    = (const float*)d_in[4];
    const float* b0    = (const float*)d_in[5];
    const float* gg0   = (const float*)d_in[6];
    const float* be0   = (const float*)d_in[7];
    const float* w1    = (const float*)d_in[8];
    const float* b1    = (const float*)d_in[9];
    const float* gg1   = (const float*)d_in[10];
    const float* be1   = (const float*)d_in[11];
    float* out = (float*)d_out;

    float *p_sum0, *p_ss0, *p_sum1, *p_ss1;
    __half *p_y1, *p_y2, *p_w0h, *p_w0l, *p_w1h, *p_w1l;
    cudaGetSymbolAddress((void**)&p_y1,   g_y1h);
    cudaGetSymbolAddress((void**)&p_y2,   g_y2h);
    cudaGetSymbolAddress((void**)&p_w0h,  g_wt0h);
    cudaGetSymbolAddress((void**)&p_w0l,  g_wt0l);
    cudaGetSymbolAddress((void**)&p_w1h,  g_wt1h);
    cudaGetSymbolAddress((void**)&p_w1l,  g_wt1l);
    cudaGetSymbolAddress((void**)&p_sum0, g_sum0);
    cudaGetSymbolAddress((void**)&p_ss0,  g_ss0);
    cudaGetSymbolAddress((void**)&p_sum1, g_sum1);
    cudaGetSymbolAddress((void**)&p_ss1,  g_ss1);

    const int smem1 = 2 * STAGE_ + 1536;  // 56832 B  (x4 CTA = 227328)
    const int smem2 = 2 * STAGE_ + 1024;  // 56320 B
    cudaFuncSetAttribute(gemm1_fused, cudaFuncAttributeMaxDynamicSharedMemorySize, smem1);
    cudaFuncSetAttribute(gemm2_mma,   cudaFuncAttributeMaxDynamicSharedMemorySize, smem2);

    knn_kernel<<<NPIX / 256, 256>>>(xyz1, xyz2);
    prep_kernel<<<(192 * 128 + 128 * 128 + 255) / 256, 256>>>(w0, w1);

    gemm1_fused<<<(NPIX / 64) * 2, 128, smem1>>>(
        feat1, feat2, p_w0h, p_w0l, b0, p_y1, p_sum0, p_ss0);

    gemm2_mma<<<(NPIX / 64) * 2, 128, smem2>>>(
        p_y1, p_w1h, p_w1l, b1, p_sum0, p_ss0, gg0, be0, p_y2, p_sum1, p_ss1);

    bn_out_kernel<<<(NPIX * 128 / 4) / 256, 256>>>(p_y2, out, p_sum1, p_ss1, gg1, be1);
}